// round 3
// baseline (speedup 1.0000x reference)
#include <cuda_runtime.h>

// Problem constants
#define HN 16      // heads
#define BN_ 2      // batch
#define SN 2048    // seq
#define DN 1024    // d_model
#define EN 64      // att_dim
#define BSN (BN_*SN)   // 4096
#define HBN (HN*BN_)   // 32

// Device scratch (allocation-free rule: __device__ globals)
__device__ float g_wt[3][DN * DN];            // 12 MB: Wq/Wk/Wv transposed to [D, H*E]
__device__ float g_prj[3][BSN * DN];          // 48 MB: qh2/kh2/vh2 in [B*S, H*E] layout
__device__ float g_cat[BSN * DN];             // 16 MB: concat(att heads) [B*S, H*E]
__device__ float g_attn_fb[(size_t)HBN * SN * SN]; // 512 MB fallback if attn not in d_out

// ---------------------------------------------------------------------------
// Weight transpose: g_wt[z][d*1024 + h*64 + e] = W_z[h*65536 + d*64 + e]
// grid: (4096, 3), block 256. Coalesced read and write.
// ---------------------------------------------------------------------------
__global__ void __launch_bounds__(256) wtrans_kernel(
    const float* __restrict__ wq, const float* __restrict__ wk, const float* __restrict__ wv)
{
    int z = blockIdx.y;
    const float* W = (z == 0) ? wq : ((z == 1) ? wk : wv);
    int idx = blockIdx.x * 256 + threadIdx.x;      // 0 .. 1048575
    int d = idx >> 10;                             // 0..1023
    int c = idx & 1023;                            // h*64 + e
    int h = c >> 6, e = c & 63;
    g_wt[z][idx] = W[(h << 16) + (d << 6) + e];
}

// ---------------------------------------------------------------------------
// Unified NN GEMM, tile 128x128x16, 256 threads, 8x8 microtile.
//   C[m,n] = sum_k A[m,k] * B[k,n],  lda = K, ldb = ldc = DN (=1024).
// mode 0..2: A = ext activation (q/k/v), B = g_wt[mode], C = g_prj[mode]
// mode 3:    A = g_cat,                  B = ext (Wo),   C = ext (out)
// grid: (M/128, DN/128) = (32, 8)
// ---------------------------------------------------------------------------
__global__ void __launch_bounds__(256) gemm_nn128(
    int mode, const float* __restrict__ Aext, const float* __restrict__ Bext,
    float* __restrict__ Cext)
{
    __shared__ float As[16][128];
    __shared__ float Bs[16][128];

    const float* A;
    const float* B;
    float* C;
    if (mode < 3) { A = Aext;  B = g_wt[mode]; C = g_prj[mode]; }
    else          { A = g_cat; B = Bext;       C = Cext; }
    const int K = DN;

    int m0 = blockIdx.x * 128;
    int n0 = blockIdx.y * 128;
    int tid = threadIdx.x;
    int lr = tid >> 1, lk8 = (tid & 1) * 8;   // A loader: row lr (0..127), 8 k's
    int bk = tid >> 4, bn = (tid & 15) * 8;   // B loader: k-row bk (0..15), 8 n's
    int ty = tid >> 4, tx = tid & 15;
    int r0 = ty * 8, c0 = tx * 8;

    float acc[8][8] = {};
    for (int kc = 0; kc < K; kc += 16) {
        const float* ap = A + (size_t)(m0 + lr) * K + kc + lk8;
        float4 a0 = *(const float4*)ap;
        float4 a1 = *(const float4*)(ap + 4);
        As[lk8 + 0][lr] = a0.x; As[lk8 + 1][lr] = a0.y;
        As[lk8 + 2][lr] = a0.z; As[lk8 + 3][lr] = a0.w;
        As[lk8 + 4][lr] = a1.x; As[lk8 + 5][lr] = a1.y;
        As[lk8 + 6][lr] = a1.z; As[lk8 + 7][lr] = a1.w;
        const float* bp = B + (size_t)(kc + bk) * DN + n0 + bn;
        *(float4*)&Bs[bk][bn]     = *(const float4*)bp;
        *(float4*)&Bs[bk][bn + 4] = *(const float4*)(bp + 4);
        __syncthreads();
#pragma unroll
        for (int k = 0; k < 16; k++) {
            float4 av0 = *(const float4*)&As[k][r0];
            float4 av1 = *(const float4*)&As[k][r0 + 4];
            float4 bv0 = *(const float4*)&Bs[k][c0];
            float4 bv1 = *(const float4*)&Bs[k][c0 + 4];
            float a[8] = {av0.x, av0.y, av0.z, av0.w, av1.x, av1.y, av1.z, av1.w};
            float b[8] = {bv0.x, bv0.y, bv0.z, bv0.w, bv1.x, bv1.y, bv1.z, bv1.w};
#pragma unroll
            for (int i = 0; i < 8; i++)
#pragma unroll
                for (int j = 0; j < 8; j++)
                    acc[i][j] += a[i] * b[j];
        }
        __syncthreads();
    }
#pragma unroll
    for (int i = 0; i < 8; i++) {
        float* cp = C + (size_t)(m0 + r0 + i) * DN + n0 + c0;
        *(float4*)cp       = make_float4(acc[i][0], acc[i][1], acc[i][2], acc[i][3]);
        *(float4*)(cp + 4) = make_float4(acc[i][4], acc[i][5], acc[i][6], acc[i][7]);
    }
}

// ---------------------------------------------------------------------------
// Scores (NT): attn_raw[hb, q, k] = (1/64) * sum_e qh2[bq, h*64+e] * kh2[bk, h*64+e]
// tile 128x128x16 over (q, k); K-dim = E = 64. grid: (16, 16, 32)
// ---------------------------------------------------------------------------
__global__ void __launch_bounds__(256) scores_nt(float* attn_arg)
{
    __shared__ float As[16][128];
    __shared__ float Bs[16][128];

    float* attn = attn_arg ? attn_arg : g_attn_fb;
    int hb = blockIdx.z;                 // hb = h*2 + b  (attn layout [H,B,Sq,Sk])
    int h = hb >> 1, b = hb & 1;
    const float* Abase = g_prj[0] + (size_t)b * SN * DN + h * EN;   // qh2, ld = DN
    const float* Bbase = g_prj[1] + (size_t)b * SN * DN + h * EN;   // kh2, ld = DN
    float* C = attn + (size_t)hb * SN * SN;

    int m0 = blockIdx.x * 128;
    int n0 = blockIdx.y * 128;
    int tid = threadIdx.x;
    int lr = tid >> 1, lk8 = (tid & 1) * 8;
    int ty = tid >> 4, tx = tid & 15;
    int r0 = ty * 8, c0 = tx * 8;

    float acc[8][8] = {};
    for (int kc = 0; kc < EN; kc += 16) {
        const float* ap = Abase + (size_t)(m0 + lr) * DN + kc + lk8;
        float4 a0 = *(const float4*)ap;
        float4 a1 = *(const float4*)(ap + 4);
        As[lk8 + 0][lr] = a0.x; As[lk8 + 1][lr] = a0.y;
        As[lk8 + 2][lr] = a0.z; As[lk8 + 3][lr] = a0.w;
        As[lk8 + 4][lr] = a1.x; As[lk8 + 5][lr] = a1.y;
        As[lk8 + 6][lr] = a1.z; As[lk8 + 7][lr] = a1.w;
        const float* bp = Bbase + (size_t)(n0 + lr) * DN + kc + lk8;
        float4 b0 = *(const float4*)bp;
        float4 b1 = *(const float4*)(bp + 4);
        Bs[lk8 + 0][lr] = b0.x; Bs[lk8 + 1][lr] = b0.y;
        Bs[lk8 + 2][lr] = b0.z; Bs[lk8 + 3][lr] = b0.w;
        Bs[lk8 + 4][lr] = b1.x; Bs[lk8 + 5][lr] = b1.y;
        Bs[lk8 + 6][lr] = b1.z; Bs[lk8 + 7][lr] = b1.w;
        __syncthreads();
#pragma unroll
        for (int k = 0; k < 16; k++) {
            float4 av0 = *(const float4*)&As[k][r0];
            float4 av1 = *(const float4*)&As[k][r0 + 4];
            float4 bv0 = *(const float4*)&Bs[k][c0];
            float4 bv1 = *(const float4*)&Bs[k][c0 + 4];
            float a[8] = {av0.x, av0.y, av0.z, av0.w, av1.x, av1.y, av1.z, av1.w};
            float b[8] = {bv0.x, bv0.y, bv0.z, bv0.w, bv1.x, bv1.y, bv1.z, bv1.w};
#pragma unroll
            for (int i = 0; i < 8; i++)
#pragma unroll
                for (int j = 0; j < 8; j++)
                    acc[i][j] += a[i] * b[j];
        }
        __syncthreads();
    }
    const float sc = 1.0f / 64.0f;
#pragma unroll
    for (int i = 0; i < 8; i++) {
        float* cp = C + (size_t)(m0 + r0 + i) * SN + n0 + c0;
        *(float4*)cp       = make_float4(acc[i][0] * sc, acc[i][1] * sc, acc[i][2] * sc, acc[i][3] * sc);
        *(float4*)(cp + 4) = make_float4(acc[i][4] * sc, acc[i][5] * sc, acc[i][6] * sc, acc[i][7] * sc);
    }
}

// ---------------------------------------------------------------------------
// Row softmax in place over attn rows of length S=2048. One block per row.
// (kept identical to round 2 — verified correct by inspection)
// ---------------------------------------------------------------------------
__global__ void __launch_bounds__(256) softmax_kernel(float* attn_arg)
{
    float* attn = attn_arg ? attn_arg : g_attn_fb;
    size_t row = blockIdx.x;
    float* p = attn + row * (size_t)SN;
    int tid = threadIdx.x;

    float4 v0 = *(float4*)(p + tid * 8);
    float4 v1 = *(float4*)(p + tid * 8 + 4);

    float m = fmaxf(fmaxf(fmaxf(v0.x, v0.y), fmaxf(v0.z, v0.w)),
                    fmaxf(fmaxf(v1.x, v1.y), fmaxf(v1.z, v1.w)));
    __shared__ float sm[8];
#pragma unroll
    for (int o = 16; o > 0; o >>= 1) m = fmaxf(m, __shfl_xor_sync(0xffffffffu, m, o));
    if ((tid & 31) == 0) sm[tid >> 5] = m;
    __syncthreads();
    if (tid < 32) {
        float t = (tid < 8) ? sm[tid] : -3.0e38f;
#pragma unroll
        for (int o = 4; o > 0; o >>= 1) t = fmaxf(t, __shfl_xor_sync(0xffffffffu, t, o));
        if (tid == 0) sm[0] = t;
    }
    __syncthreads();
    m = sm[0];
    __syncthreads();

    float e0 = __expf(v0.x - m), e1 = __expf(v0.y - m), e2 = __expf(v0.z - m), e3 = __expf(v0.w - m);
    float e4 = __expf(v1.x - m), e5 = __expf(v1.y - m), e6 = __expf(v1.z - m), e7 = __expf(v1.w - m);
    float s = ((e0 + e1) + (e2 + e3)) + ((e4 + e5) + (e6 + e7));
#pragma unroll
    for (int o = 16; o > 0; o >>= 1) s += __shfl_xor_sync(0xffffffffu, s, o);
    if ((tid & 31) == 0) sm[tid >> 5] = s;
    __syncthreads();
    if (tid < 32) {
        float t = (tid < 8) ? sm[tid] : 0.0f;
#pragma unroll
        for (int o = 4; o > 0; o >>= 1) t += __shfl_xor_sync(0xffffffffu, t, o);
        if (tid == 0) sm[0] = t;
    }
    __syncthreads();
    float inv = 1.0f / sm[0];

    *(float4*)(p + tid * 8)     = make_float4(e0 * inv, e1 * inv, e2 * inv, e3 * inv);
    *(float4*)(p + tid * 8 + 4) = make_float4(e4 * inv, e5 * inv, e6 * inv, e7 * inv);
}

// ---------------------------------------------------------------------------
// att (NN, N=64): g_cat[b*S+s, h*64+e] = sum_k attn[hb, s, k] * vh2[b*S+k, h*64+e]
// tile 128x64x16, 8x4 microtile. grid: (16, 1, 32). K = S = 2048.
// ---------------------------------------------------------------------------
__global__ void __launch_bounds__(256) att_nn64(const float* attn_arg)
{
    __shared__ float As[16][128];
    __shared__ float Bs[16][64];

    const float* attn = attn_arg ? attn_arg : g_attn_fb;
    int hb = blockIdx.z;
    int h = hb >> 1, b = hb & 1;
    const float* A = attn + (size_t)hb * SN * SN;                 // [S, S], lda = SN
    const float* B = g_prj[2] + (size_t)b * SN * DN + h * EN;     // vh2, ldb = DN
    float* C       = g_cat    + (size_t)b * SN * DN + h * EN;     // ldc = DN

    int m0 = blockIdx.x * 128;
    int tid = threadIdx.x;
    int lr = tid >> 1, lk8 = (tid & 1) * 8;
    int bk = tid >> 4, bn = (tid & 15) * 4;
    int ty = tid >> 4, tx = tid & 15;
    int r0 = ty * 8, c0 = tx * 4;

    float acc[8][4] = {};
    for (int kc = 0; kc < SN; kc += 16) {
        const float* ap = A + (size_t)(m0 + lr) * SN + kc + lk8;
        float4 a0 = *(const float4*)ap;
        float4 a1 = *(const float4*)(ap + 4);
        As[lk8 + 0][lr] = a0.x; As[lk8 + 1][lr] = a0.y;
        As[lk8 + 2][lr] = a0.z; As[lk8 + 3][lr] = a0.w;
        As[lk8 + 4][lr] = a1.x; As[lk8 + 5][lr] = a1.y;
        As[lk8 + 6][lr] = a1.z; As[lk8 + 7][lr] = a1.w;
        *(float4*)&Bs[bk][bn] = *(const float4*)(B + (size_t)(kc + bk) * DN + bn);
        __syncthreads();
#pragma unroll
        for (int k = 0; k < 16; k++) {
            float4 av0 = *(const float4*)&As[k][r0];
            float4 av1 = *(const float4*)&As[k][r0 + 4];
            float4 bv  = *(const float4*)&Bs[k][c0];
            float a[8] = {av0.x, av0.y, av0.z, av0.w, av1.x, av1.y, av1.z, av1.w};
            float b[4] = {bv.x, bv.y, bv.z, bv.w};
#pragma unroll
            for (int i = 0; i < 8; i++)
#pragma unroll
                for (int j = 0; j < 4; j++)
                    acc[i][j] += a[i] * b[j];
        }
        __syncthreads();
    }
#pragma unroll
    for (int i = 0; i < 8; i++) {
        *(float4*)(C + (size_t)(m0 + r0 + i) * DN + c0) =
            make_float4(acc[i][0], acc[i][1], acc[i][2], acc[i][3]);
    }
}

// ---------------------------------------------------------------------------
extern "C" void kernel_launch(void* const* d_in, const int* in_sizes, int n_in,
                              void* d_out, int out_size)
{
    // Map inputs by element count: activations (B*S*D = 4,194,304) in order q,k,v;
    // weights (1,048,576) in order Wq,Wk,Wv,Wo. Falls back to positional if counts差.
    const float* acts[3] = {nullptr, nullptr, nullptr};
    const float* wts[4]  = {nullptr, nullptr, nullptr, nullptr};
    int na = 0, nw = 0;
    for (int i = 0; i < n_in; i++) {
        if (in_sizes[i] == BSN * DN && na < 3) acts[na++] = (const float*)d_in[i];
        else if (nw < 4)                       wts[nw++]  = (const float*)d_in[i];
    }
    if (na != 3 || nw != 4) {
        acts[0] = (const float*)d_in[0]; acts[1] = (const float*)d_in[1]; acts[2] = (const float*)d_in[2];
        wts[0]  = (const float*)d_in[3]; wts[1]  = (const float*)d_in[4];
        wts[2]  = (const float*)d_in[5]; wts[3]  = (const float*)d_in[6];
    }
    const float* q  = acts[0];
    const float* k  = acts[1];
    const float* v  = acts[2];
    const float* Wq = wts[0];
    const float* Wk = wts[1];
    const float* Wv = wts[2];
    const float* Wo = wts[3];
    float* out = (float*)d_out;

    const long long OUT_E  = (long long)BSN * DN;          // 4,194,304
    const long long ATTN_E = (long long)HBN * SN * SN;     // 134,217,728
    float* attn_ptr = ((long long)out_size >= OUT_E + ATTN_E) ? (out + OUT_E) : nullptr;

    dim3 blk(256);
    wtrans_kernel<<<dim3(DN * DN / 256, 3), blk>>>(Wq, Wk, Wv);
    gemm_nn128<<<dim3(BSN / 128, DN / 128), blk>>>(0, q, nullptr, nullptr);
    gemm_nn128<<<dim3(BSN / 128, DN / 128), blk>>>(1, k, nullptr, nullptr);
    gemm_nn128<<<dim3(BSN / 128, DN / 128), blk>>>(2, v, nullptr, nullptr);
    scores_nt<<<dim3(SN / 128, SN / 128, HBN), blk>>>(attn_ptr);
    softmax_kernel<<<dim3(HBN * SN), blk>>>(attn_ptr);
    att_nn64<<<dim3(SN / 128, 1, HBN), blk>>>(attn_ptr);
    gemm_nn128<<<dim3(BSN / 128, DN / 128), blk>>>(3, nullptr, Wo, out);
}

// round 8
// speedup vs baseline: 1.3489x; 1.3489x over previous
#include <cuda_runtime.h>
#include <cuda_bf16.h>
#include <cstdint>

#define HN 16
#define BN_ 2
#define SN 2048
#define DN 1024
#define EN 64
#define BSN 4096
#define HBN 32

// ---------------- device scratch (allocation-free rule) ----------------
__device__ __align__(256) __nv_bfloat16 g_w_hi[4][DN * DN];   // [z][n][k]  z=0..2: W{q,k,v} as [h*64+e][d]; z=3: Wo^T [n][k]
__device__ __align__(256) __nv_bfloat16 g_w_lo[4][DN * DN];
__device__ __align__(256) __nv_bfloat16 g_p_hi[3][BSN * DN];  // qh/kh/vh split, [b*S+s][h*64+e]
__device__ __align__(256) __nv_bfloat16 g_p_lo[3][BSN * DN];
__device__ __align__(256) __nv_bfloat16 g_vt_hi[HBN][EN * SN]; // V^T per head: [hb][e][s]
__device__ __align__(256) __nv_bfloat16 g_vt_lo[HBN][EN * SN];
__device__ __align__(256) __nv_bfloat16 g_cat_hi[BSN * DN];
__device__ __align__(256) __nv_bfloat16 g_cat_lo[BSN * DN];
__device__ __align__(256) float g_attn_fb[(size_t)HBN * SN * SN];

// ---------------- helpers ----------------
__device__ __forceinline__ uint32_t smem_u32(const void* p) {
    uint32_t a;
    asm("{ .reg .u64 t; cvta.to.shared.u64 t, %1; cvt.u32.u64 %0, t; }" : "=r"(a) : "l"(p));
    return a;
}
#define SWZ(x) ((x) ^ (((x) >> 3) & 0x70))

__device__ __forceinline__ void sts128(uint32_t addr, uint4 v) {
    asm volatile("st.shared.v4.b32 [%0], {%1,%2,%3,%4};"
                 :: "r"(addr), "r"(v.x), "r"(v.y), "r"(v.z), "r"(v.w) : "memory");
}

// pack two floats into bf16x2; 'a' -> low element, 'b' -> high element
__device__ __forceinline__ uint32_t bpair(float a, float b) {
    uint32_t r;
    asm("cvt.rn.bf16x2.f32 %0, %1, %2;" : "=r"(r) : "f"(b), "f"(a));
    return r;
}

__device__ __forceinline__ void ldmx4(uint32_t* r, uint32_t addr) {
    asm volatile("ldmatrix.sync.aligned.m8n8.x4.shared.b16 {%0,%1,%2,%3}, [%4];"
                 : "=r"(r[0]), "=r"(r[1]), "=r"(r[2]), "=r"(r[3]) : "r"(addr));
}

__device__ __forceinline__ void mma16816(float* d, const uint32_t* a, const uint32_t* b) {
    asm volatile("mma.sync.aligned.m16n8k16.row.col.f32.bf16.bf16.f32 "
        "{%0,%1,%2,%3}, {%4,%5,%6,%7}, {%8,%9}, {%0,%1,%2,%3};"
        : "+f"(d[0]), "+f"(d[1]), "+f"(d[2]), "+f"(d[3])
        : "r"(a[0]), "r"(a[1]), "r"(a[2]), "r"(a[3]), "r"(b[0]), "r"(b[1]));
}

// split-write two consecutive fp32 -> bf16x2 hi + bf16x2 lo
__device__ __forceinline__ void store_split2(__nv_bfloat16* Chi, __nv_bfloat16* Clo,
                                             size_t off, float v0, float v1) {
    float h0 = __bfloat162float(__float2bfloat16(v0));
    float h1 = __bfloat162float(__float2bfloat16(v1));
    *(uint32_t*)(Chi + off) = bpair(h0, h1);
    *(uint32_t*)(Clo + off) = bpair(v0 - h0, v1 - h1);
}

// SMEM layout (dynamic): tiles of 128B-swizzled rows (64 bf16 per row)
#define SM_AH 0
#define SM_AL 16384
#define SM_BH 32768
#define SM_BL 49152
#define SMEM_N128 65536
#define SM_BH2 32768            // att: B tiles are 64 rows = 8KB
#define SM_BL2 40960
#define SMEM_N64 49152

// Load 128 rows x 64 cols fp32 -> split bf16 hi/lo into swizzled smem tiles.
__device__ __forceinline__ void load_split_f32(uint32_t dhi, uint32_t dlo,
                                               const float* __restrict__ src, int ld, int tid) {
#pragma unroll
    for (int it = 0; it < 4; it++) {
        int c = tid + it * 256;          // 1024 chunks of 8 elems
        int r = c >> 3, g = c & 7;
        const float* p = src + (size_t)r * ld + g * 8;
        float4 f0 = *(const float4*)p;
        float4 f1 = *(const float4*)(p + 4);
        float v[8] = {f0.x, f0.y, f0.z, f0.w, f1.x, f1.y, f1.z, f1.w};
        uint4 H, L;
        uint32_t* Hp = (uint32_t*)&H;
        uint32_t* Lp = (uint32_t*)&L;
#pragma unroll
        for (int pp = 0; pp < 4; pp++) {
            float h0 = __bfloat162float(__float2bfloat16(v[pp * 2]));
            float h1 = __bfloat162float(__float2bfloat16(v[pp * 2 + 1]));
            Hp[pp] = bpair(h0, h1);
            Lp[pp] = bpair(v[pp * 2] - h0, v[pp * 2 + 1] - h1);
        }
        uint32_t ad = SWZ((uint32_t)(r * 128 + g * 16));
        sts128(dhi + ad, H);
        sts128(dlo + ad, L);
    }
}

// Load `rows` x 64 bf16 into swizzled smem (rows*8 16B chunks).
__device__ __forceinline__ void load_b16(uint32_t dst, const __nv_bfloat16* __restrict__ src,
                                         int ld, int tid, int rows) {
    int nchunk = rows * 8;
    for (int c = tid; c < nchunk; c += 256) {
        int r = c >> 3, g = c & 7;
        uint4 v = *(const uint4*)(src + (size_t)r * ld + g * 8);
        sts128(dst + SWZ((uint32_t)(r * 128 + g * 16)), v);
    }
}

// ---------------------------------------------------------------------------
// Weight transpose+split: W{q,k,v}[h][d][e] -> g_w[z][n=h*64+e][k=d]
// ---------------------------------------------------------------------------
__global__ void __launch_bounds__(256) wsplit_qkv(
    const float* __restrict__ wq, const float* __restrict__ wk, const float* __restrict__ wv)
{
    __shared__ float tile[32][33];
    int z = blockIdx.z >> 4, h = blockIdx.z & 15;
    const float* W = (z == 0) ? wq : ((z == 1) ? wk : wv);
    int d0 = blockIdx.x * 32, e0 = blockIdx.y * 32;
    int tx = threadIdx.x, ty = threadIdx.y;
#pragma unroll
    for (int i = 0; i < 4; i++) {
        int d = d0 + ty + i * 8;
        tile[ty + i * 8][tx] = W[(size_t)h * DN * EN + (size_t)d * EN + e0 + tx];
    }
    __syncthreads();
#pragma unroll
    for (int i = 0; i < 4; i++) {
        int e = e0 + ty + i * 8;
        int n = h * EN + e, k = d0 + tx;
        float v = tile[tx][ty + i * 8];
        float hf = __bfloat162float(__float2bfloat16(v));
        g_w_hi[z][(size_t)n * DN + k] = __float2bfloat16(hf);
        g_w_lo[z][(size_t)n * DN + k] = __float2bfloat16(v - hf);
    }
}

// Wo[k][n] -> g_w[3][n][k]
__global__ void __launch_bounds__(256) wsplit_o(const float* __restrict__ wo)
{
    __shared__ float tile[32][33];
    int k0 = blockIdx.x * 32, n0 = blockIdx.y * 32;
    int tx = threadIdx.x, ty = threadIdx.y;
#pragma unroll
    for (int i = 0; i < 4; i++)
        tile[ty + i * 8][tx] = wo[(size_t)(k0 + ty + i * 8) * DN + n0 + tx];
    __syncthreads();
#pragma unroll
    for (int i = 0; i < 4; i++) {
        int n = n0 + ty + i * 8, k = k0 + tx;
        float v = tile[tx][ty + i * 8];
        float hf = __bfloat162float(__float2bfloat16(v));
        g_w_hi[3][(size_t)n * DN + k] = __float2bfloat16(hf);
        g_w_lo[3][(size_t)n * DN + k] = __float2bfloat16(v - hf);
    }
}

// V transpose: g_p[2][b*S+s][h*64+e] -> g_vt[hb][e][s]
__global__ void __launch_bounds__(256) vtrans_kernel()
{
    __shared__ __nv_bfloat16 th[32][33];
    __shared__ __nv_bfloat16 tl[32][33];
    int hb = blockIdx.z, h = hb >> 1, b = hb & 1;
    int s0 = blockIdx.x * 32, e0 = blockIdx.y * 32;
    int tx = threadIdx.x, ty = threadIdx.y;
#pragma unroll
    for (int i = 0; i < 4; i++) {
        size_t src = (size_t)(b * SN + s0 + ty + i * 8) * DN + h * EN + e0 + tx;
        th[ty + i * 8][tx] = g_p_hi[2][src];
        tl[ty + i * 8][tx] = g_p_lo[2][src];
    }
    __syncthreads();
#pragma unroll
    for (int i = 0; i < 4; i++) {
        int e = e0 + ty + i * 8;
        size_t dst = (size_t)e * SN + s0 + tx;
        g_vt_hi[hb][dst] = th[tx][ty + i * 8];
        g_vt_lo[hb][dst] = tl[tx][ty + i * 8];
    }
}

// ===========================================================================
// mma.sync core: one 64-K chunk on a 128x128 tile (8 warps as 2x4, 64x32/warp)
// acc[4][4][4]; A/B in swizzled smem (hi/lo each).
// ===========================================================================
__device__ __forceinline__ void mma_chunk_128(float acc[4][4][4], uint32_t sb,
                                              int wm, int wn, int lane) {
#pragma unroll
    for (int ks = 0; ks < 4; ks++) {
        uint32_t ah[4][4], al[4][4], bh[4][2], bl[4][2];
        int acol = ks * 32 + (lane >> 4) * 16;
#pragma unroll
        for (int mi = 0; mi < 4; mi++) {
            int arow = wm * 64 + mi * 16 + (lane & 15);
            uint32_t off = SWZ((uint32_t)(arow * 128 + acol));
            ldmx4(ah[mi], sb + SM_AH + off);
            ldmx4(al[mi], sb + SM_AL + off);
        }
        int bcol = ks * 32 + ((lane >> 3) & 1) * 16;
#pragma unroll
        for (int nj = 0; nj < 2; nj++) {
            int brow = wn * 32 + nj * 16 + (lane & 7) + (lane >> 4) * 8;
            uint32_t off = SWZ((uint32_t)(brow * 128 + bcol));
            uint32_t t[4];
            ldmx4(t, sb + SM_BH + off);
            bh[nj * 2][0] = t[0]; bh[nj * 2][1] = t[1];
            bh[nj * 2 + 1][0] = t[2]; bh[nj * 2 + 1][1] = t[3];
            ldmx4(t, sb + SM_BL + off);
            bl[nj * 2][0] = t[0]; bl[nj * 2][1] = t[1];
            bl[nj * 2 + 1][0] = t[2]; bl[nj * 2 + 1][1] = t[3];
        }
#pragma unroll
        for (int mi = 0; mi < 4; mi++)
#pragma unroll
            for (int ni = 0; ni < 4; ni++) {
                mma16816(acc[mi][ni], ah[mi], bh[ni]);
                mma16816(acc[mi][ni], ah[mi], bl[ni]);
                mma16816(acc[mi][ni], al[mi], bh[ni]);
            }
    }
}

// ---------------------------------------------------------------------------
// Projection GEMM: qh/kh/vh[m, n] = sum_k x[m,k] * Wt[n,k].  M=4096, N=1024, K=1024.
// grid (32, 8, 3), block 256; output split into bf16 hi/lo.
// ---------------------------------------------------------------------------
__global__ void __launch_bounds__(256) gemm_proj(
    const float* __restrict__ q, const float* __restrict__ k, const float* __restrict__ v)
{
    extern __shared__ char smem[];
    uint32_t sb = smem_u32(smem);
    int tid = threadIdx.x, wid = tid >> 5, lane = tid & 31;
    int z = blockIdx.z;
    const float* A = (z == 0) ? q : ((z == 1) ? k : v);
    const __nv_bfloat16* Bhi = g_w_hi[z];
    const __nv_bfloat16* Blo = g_w_lo[z];
    __nv_bfloat16* Chi = g_p_hi[z];
    __nv_bfloat16* Clo = g_p_lo[z];
    int m0 = blockIdx.x * 128, n0 = blockIdx.y * 128;
    int wm = wid & 1, wn = wid >> 1;

    float acc[4][4][4] = {};
    for (int kc = 0; kc < DN; kc += 64) {
        __syncthreads();
        load_split_f32(sb + SM_AH, sb + SM_AL, A + (size_t)m0 * DN + kc, DN, tid);
        load_b16(sb + SM_BH, Bhi + (size_t)n0 * DN + kc, DN, tid, 128);
        load_b16(sb + SM_BL, Blo + (size_t)n0 * DN + kc, DN, tid, 128);
        __syncthreads();
        mma_chunk_128(acc, sb, wm, wn, lane);
    }

    size_t rbase = (size_t)m0 + wm * 64;
    int cbase = n0 + wn * 32;
#pragma unroll
    for (int mi = 0; mi < 4; mi++)
#pragma unroll
        for (int ni = 0; ni < 4; ni++) {
            size_t r0 = rbase + mi * 16 + (lane >> 2);
            int c = cbase + ni * 8 + (lane & 3) * 2;
            store_split2(Chi, Clo, r0 * DN + c,       acc[mi][ni][0], acc[mi][ni][1]);
            store_split2(Chi, Clo, (r0 + 8) * DN + c, acc[mi][ni][2], acc[mi][ni][3]);
        }
}

// ---------------------------------------------------------------------------
// Scores GEMM (K=64): attn[hb, m, n] = (1/64) sum_e qh*kh.  grid (16,16,32)
// ---------------------------------------------------------------------------
__global__ void __launch_bounds__(256) gemm_scores(float* attn_arg)
{
    extern __shared__ char smem[];
    uint32_t sb = smem_u32(smem);
    int tid = threadIdx.x, wid = tid >> 5, lane = tid & 31;
    float* attn = attn_arg ? attn_arg : g_attn_fb;
    int hb = blockIdx.z, h = hb >> 1, b = hb & 1;
    int m0 = blockIdx.x * 128, n0 = blockIdx.y * 128;
    const __nv_bfloat16* Ah = g_p_hi[0] + (size_t)(b * SN + m0) * DN + h * EN;
    const __nv_bfloat16* Al = g_p_lo[0] + (size_t)(b * SN + m0) * DN + h * EN;
    const __nv_bfloat16* Bh = g_p_hi[1] + (size_t)(b * SN + n0) * DN + h * EN;
    const __nv_bfloat16* Bl = g_p_lo[1] + (size_t)(b * SN + n0) * DN + h * EN;
    float* C = attn + (size_t)hb * SN * SN;
    int wm = wid & 1, wn = wid >> 1;

    load_b16(sb + SM_AH, Ah, DN, tid, 128);
    load_b16(sb + SM_AL, Al, DN, tid, 128);
    load_b16(sb + SM_BH, Bh, DN, tid, 128);
    load_b16(sb + SM_BL, Bl, DN, tid, 128);
    __syncthreads();

    float acc[4][4][4] = {};
    mma_chunk_128(acc, sb, wm, wn, lane);

    const float sc = 1.0f / 64.0f;
    size_t rbase = (size_t)m0 + wm * 64;
    int cbase = n0 + wn * 32;
#pragma unroll
    for (int mi = 0; mi < 4; mi++)
#pragma unroll
        for (int ni = 0; ni < 4; ni++) {
            size_t r0 = rbase + mi * 16 + (lane >> 2);
            int c = cbase + ni * 8 + (lane & 3) * 2;
            *(float2*)(C + r0 * SN + c)       = make_float2(acc[mi][ni][0] * sc, acc[mi][ni][1] * sc);
            *(float2*)(C + (r0 + 8) * SN + c) = make_float2(acc[mi][ni][2] * sc, acc[mi][ni][3] * sc);
        }
}

// ---------------------------------------------------------------------------
// Row softmax in place, rows of length 2048. One block per row. (unchanged)
// ---------------------------------------------------------------------------
__global__ void __launch_bounds__(256) softmax_kernel(float* attn_arg)
{
    float* attn = attn_arg ? attn_arg : g_attn_fb;
    size_t row = blockIdx.x;
    float* p = attn + row * (size_t)SN;
    int tid = threadIdx.x;

    float4 v0 = *(float4*)(p + tid * 8);
    float4 v1 = *(float4*)(p + tid * 8 + 4);

    float m = fmaxf(fmaxf(fmaxf(v0.x, v0.y), fmaxf(v0.z, v0.w)),
                    fmaxf(fmaxf(v1.x, v1.y), fmaxf(v1.z, v1.w)));
    __shared__ float sm[8];
#pragma unroll
    for (int o = 16; o > 0; o >>= 1) m = fmaxf(m, __shfl_xor_sync(0xffffffffu, m, o));
    if ((tid & 31) == 0) sm[tid >> 5] = m;
    __syncthreads();
    if (tid < 32) {
        float t = (tid < 8) ? sm[tid] : -3.0e38f;
#pragma unroll
        for (int o = 4; o > 0; o >>= 1) t = fmaxf(t, __shfl_xor_sync(0xffffffffu, t, o));
        if (tid == 0) sm[0] = t;
    }
    __syncthreads();
    m = sm[0];
    __syncthreads();

    float e0 = __expf(v0.x - m), e1 = __expf(v0.y - m), e2 = __expf(v0.z - m), e3 = __expf(v0.w - m);
    float e4 = __expf(v1.x - m), e5 = __expf(v1.y - m), e6 = __expf(v1.z - m), e7 = __expf(v1.w - m);
    float s = ((e0 + e1) + (e2 + e3)) + ((e4 + e5) + (e6 + e7));
#pragma unroll
    for (int o = 16; o > 0; o >>= 1) s += __shfl_xor_sync(0xffffffffu, s, o);
    if ((tid & 31) == 0) sm[tid >> 5] = s;
    __syncthreads();
    if (tid < 32) {
        float t = (tid < 8) ? sm[tid] : 0.0f;
#pragma unroll
        for (int o = 4; o > 0; o >>= 1) t += __shfl_xor_sync(0xffffffffu, t, o);
        if (tid == 0) sm[0] = t;
    }
    __syncthreads();
    float inv = 1.0f / sm[0];

    *(float4*)(p + tid * 8)     = make_float4(e0 * inv, e1 * inv, e2 * inv, e3 * inv);
    *(float4*)(p + tid * 8 + 4) = make_float4(e4 * inv, e5 * inv, e6 * inv, e7 * inv);
}

// ---------------------------------------------------------------------------
// att GEMM: cat[b*S+m, h*64+e] = sum_k attn[hb,m,k] * vt[hb,e,k]. N=64, K=2048.
// grid (16, 1, 32), 8 warps as 4x2, warp tile 32x32.
// ---------------------------------------------------------------------------
__global__ void __launch_bounds__(256) gemm_att(const float* attn_arg)
{
    extern __shared__ char smem[];
    uint32_t sb = smem_u32(smem);
    int tid = threadIdx.x, wid = tid >> 5, lane = tid & 31;
    const float* attn = attn_arg ? attn_arg : g_attn_fb;
    int hb = blockIdx.z, h = hb >> 1, b = hb & 1;
    int m0 = blockIdx.x * 128;
    const float* A = attn + (size_t)hb * SN * SN + (size_t)m0 * SN;
    int wm = wid & 3, wn = wid >> 2;

    float acc[2][4][4] = {};
    for (int kc = 0; kc < SN; kc += 64) {
        __syncthreads();
        load_split_f32(sb + SM_AH, sb + SM_AL, A + kc, SN, tid);
        load_b16(sb + SM_BH2, g_vt_hi[hb] + kc, SN, tid, 64);
        load_b16(sb + SM_BL2, g_vt_lo[hb] + kc, SN, tid, 64);
        __syncthreads();
#pragma unroll
        for (int ks = 0; ks < 4; ks++) {
            uint32_t ah[2][4], al[2][4], bh[4][2], bl[4][2];
            int acol = ks * 32 + (lane >> 4) * 16;
#pragma unroll
            for (int mi = 0; mi < 2; mi++) {
                int arow = wm * 32 + mi * 16 + (lane & 15);
                uint32_t off = SWZ((uint32_t)(arow * 128 + acol));
                ldmx4(ah[mi], sb + SM_AH + off);
                ldmx4(al[mi], sb + SM_AL + off);
            }
            int bcol = ks * 32 + ((lane >> 3) & 1) * 16;
#pragma unroll
            for (int nj = 0; nj < 2; nj++) {
                int brow = wn * 32 + nj * 16 + (lane & 7) + (lane >> 4) * 8;
                uint32_t off = SWZ((uint32_t)(brow * 128 + bcol));
                uint32_t t[4];
                ldmx4(t, sb + SM_BH2 + off);
                bh[nj * 2][0] = t[0]; bh[nj * 2][1] = t[1];
                bh[nj * 2 + 1][0] = t[2]; bh[nj * 2 + 1][1] = t[3];
                ldmx4(t, sb + SM_BL2 + off);
                bl[nj * 2][0] = t[0]; bl[nj * 2][1] = t[1];
                bl[nj * 2 + 1][0] = t[2]; bl[nj * 2 + 1][1] = t[3];
            }
#pragma unroll
            for (int mi = 0; mi < 2; mi++)
#pragma unroll
                for (int ni = 0; ni < 4; ni++) {
                    mma16816(acc[mi][ni], ah[mi], bh[ni]);
                    mma16816(acc[mi][ni], ah[mi], bl[ni]);
                    mma16816(acc[mi][ni], al[mi], bh[ni]);
                }
        }
    }

    size_t rbase = (size_t)(b * SN + m0) + wm * 32;
    int cbase = h * EN + wn * 32;
#pragma unroll
    for (int mi = 0; mi < 2; mi++)
#pragma unroll
        for (int ni = 0; ni < 4; ni++) {
            size_t r0 = rbase + mi * 16 + (lane >> 2);
            int c = cbase + ni * 8 + (lane & 3) * 2;
            store_split2(g_cat_hi, g_cat_lo, r0 * DN + c,       acc[mi][ni][0], acc[mi][ni][1]);
            store_split2(g_cat_hi, g_cat_lo, (r0 + 8) * DN + c, acc[mi][ni][2], acc[mi][ni][3]);
        }
}

// ---------------------------------------------------------------------------
// Output GEMM: out[m, n] = sum_k cat[m,k] * WoT[n,k]. M=4096, N=1024, K=1024.
// grid (32, 8)
// ---------------------------------------------------------------------------
__global__ void __launch_bounds__(256) gemm_out(float* __restrict__ out)
{
    extern __shared__ char smem[];
    uint32_t sb = smem_u32(smem);
    int tid = threadIdx.x, wid = tid >> 5, lane = tid & 31;
    int m0 = blockIdx.x * 128, n0 = blockIdx.y * 128;
    int wm = wid & 1, wn = wid >> 1;

    float acc[4][4][4] = {};
    for (int kc = 0; kc < DN; kc += 64) {
        __syncthreads();
        load_b16(sb + SM_AH, g_cat_hi + (size_t)m0 * DN + kc, DN, tid, 128);
        load_b16(sb + SM_AL, g_cat_lo + (size_t)m0 * DN + kc, DN, tid, 128);
        load_b16(sb + SM_BH, g_w_hi[3] + (size_t)n0 * DN + kc, DN, tid, 128);
        load_b16(sb + SM_BL, g_w_lo[3] + (size_t)n0 * DN + kc, DN, tid, 128);
        __syncthreads();
        mma_chunk_128(acc, sb, wm, wn, lane);
    }

    size_t rbase = (size_t)m0 + wm * 64;
    int cbase = n0 + wn * 32;
#pragma unroll
    for (int mi = 0; mi < 4; mi++)
#pragma unroll
        for (int ni = 0; ni < 4; ni++) {
            size_t r0 = rbase + mi * 16 + (lane >> 2);
            int c = cbase + ni * 8 + (lane & 3) * 2;
            *(float2*)(out + r0 * DN + c)       = make_float2(acc[mi][ni][0], acc[mi][ni][1]);
            *(float2*)(out + (r0 + 8) * DN + c) = make_float2(acc[mi][ni][2], acc[mi][ni][3]);
        }
}

// ---------------------------------------------------------------------------
extern "C" void kernel_launch(void* const* d_in, const int* in_sizes, int n_in,
                              void* d_out, int out_size)
{
    const float* acts[3] = {nullptr, nullptr, nullptr};
    const float* wts[4]  = {nullptr, nullptr, nullptr, nullptr};
    int na = 0, nw = 0;
    for (int i = 0; i < n_in; i++) {
        if (in_sizes[i] == BSN * DN && na < 3) acts[na++] = (const float*)d_in[i];
        else if (nw < 4)                       wts[nw++]  = (const float*)d_in[i];
    }
    if (na != 3 || nw != 4) {
        acts[0] = (const float*)d_in[0]; acts[1] = (const float*)d_in[1]; acts[2] = (const float*)d_in[2];
        wts[0]  = (const float*)d_in[3]; wts[1]  = (const float*)d_in[4];
        wts[2]  = (const float*)d_in[5]; wts[3]  = (const float*)d_in[6];
    }
    const float* q  = acts[0];
    const float* k  = acts[1];
    const float* v  = acts[2];
    const float* Wq = wts[0];
    const float* Wk = wts[1];
    const float* Wv = wts[2];
    const float* Wo = wts[3];
    float* out = (float*)d_out;

    const long long OUT_E  = (long long)BSN * DN;
    const long long ATTN_E = (long long)HBN * SN * SN;
    float* attn_ptr = ((long long)out_size >= OUT_E + ATTN_E) ? (out + OUT_E) : nullptr;

    cudaFuncSetAttribute(gemm_proj,   cudaFuncAttributeMaxDynamicSharedMemorySize, SMEM_N128);
    cudaFuncSetAttribute(gemm_scores, cudaFuncAttributeMaxDynamicSharedMemorySize, SMEM_N128);
    cudaFuncSetAttribute(gemm_att,    cudaFuncAttributeMaxDynamicSharedMemorySize, SMEM_N64);
    cudaFuncSetAttribute(gemm_out,    cudaFuncAttributeMaxDynamicSharedMemorySize, SMEM_N128);

    wsplit_qkv<<<dim3(32, 2, 48), dim3(32, 8)>>>(Wq, Wk, Wv);
    wsplit_o<<<dim3(32, 32), dim3(32, 8)>>>(Wo);
    gemm_proj<<<dim3(32, 8, 3), 256, SMEM_N128>>>(q, k, v);
    vtrans_kernel<<<dim3(64, 2, 32), dim3(32, 8)>>>();
    gemm_scores<<<dim3(16, 16, 32), 256, SMEM_N128>>>(attn_ptr);
    softmax_kernel<<<dim3(HBN * SN), 256>>>(attn_ptr);
    gemm_att<<<dim3(16, 1, 32), 256, SMEM_N64>>>(attn_ptr);
    gemm_out<<<dim3(32, 8), 256, SMEM_N128>>>(out);
}

// round 9
// speedup vs baseline: 1.9397x; 1.4380x over previous
#include <cuda_runtime.h>
#include <cuda_bf16.h>
#include <cstdint>

#define HN 16
#define BN_ 2
#define SN 2048
#define DN 1024
#define EN 64
#define BSN 4096
#define HBN 32

// ---------------- device scratch (allocation-free rule) ----------------
__device__ __align__(256) __nv_bfloat16 g_w_hi[4][DN * DN];   // [z][n][k]
__device__ __align__(256) __nv_bfloat16 g_w_lo[4][DN * DN];
__device__ __align__(256) __nv_bfloat16 g_x_hi[3][BSN * DN];  // q/k/v split [b*S+s][d]
__device__ __align__(256) __nv_bfloat16 g_x_lo[3][BSN * DN];
__device__ __align__(256) __nv_bfloat16 g_p_hi[3][BSN * DN];  // qh/kh/vh split
__device__ __align__(256) __nv_bfloat16 g_p_lo[3][BSN * DN];
__device__ __align__(256) __nv_bfloat16 g_vt_hi[HBN][EN * SN]; // V^T per head
__device__ __align__(256) __nv_bfloat16 g_vt_lo[HBN][EN * SN];
__device__ __align__(256) __nv_bfloat16 g_cat_hi[BSN * DN];
__device__ __align__(256) __nv_bfloat16 g_cat_lo[BSN * DN];
__device__ __align__(256) float g_attn_fb[(size_t)HBN * SN * SN];

// ---------------- helpers ----------------
__device__ __forceinline__ uint32_t smem_u32(const void* p) {
    uint32_t a;
    asm("{ .reg .u64 t; cvta.to.shared.u64 t, %1; cvt.u32.u64 %0, t; }" : "=r"(a) : "l"(p));
    return a;
}
#define SWZ(x) ((x) ^ (((x) >> 3) & 0x70))

__device__ __forceinline__ void sts128(uint32_t addr, uint4 v) {
    asm volatile("st.shared.v4.b32 [%0], {%1,%2,%3,%4};"
                 :: "r"(addr), "r"(v.x), "r"(v.y), "r"(v.z), "r"(v.w) : "memory");
}
__device__ __forceinline__ uint32_t bpair(float a, float b) {
    uint32_t r;
    asm("cvt.rn.bf16x2.f32 %0, %1, %2;" : "=r"(r) : "f"(b), "f"(a));
    return r;
}
__device__ __forceinline__ void ldmx4(uint32_t* r, uint32_t addr) {
    asm volatile("ldmatrix.sync.aligned.m8n8.x4.shared.b16 {%0,%1,%2,%3}, [%4];"
                 : "=r"(r[0]), "=r"(r[1]), "=r"(r[2]), "=r"(r[3]) : "r"(addr));
}
__device__ __forceinline__ void mma16816(float* d, const uint32_t* a, const uint32_t* b) {
    asm volatile("mma.sync.aligned.m16n8k16.row.col.f32.bf16.bf16.f32 "
        "{%0,%1,%2,%3}, {%4,%5,%6,%7}, {%8,%9}, {%0,%1,%2,%3};"
        : "+f"(d[0]), "+f"(d[1]), "+f"(d[2]), "+f"(d[3])
        : "r"(a[0]), "r"(a[1]), "r"(a[2]), "r"(a[3]), "r"(b[0]), "r"(b[1]));
}
__device__ __forceinline__ void store_split2(__nv_bfloat16* Chi, __nv_bfloat16* Clo,
                                             size_t off, float v0, float v1) {
    float h0 = __bfloat162float(__float2bfloat16(v0));
    float h1 = __bfloat162float(__float2bfloat16(v1));
    *(uint32_t*)(Chi + off) = bpair(h0, h1);
    *(uint32_t*)(Clo + off) = bpair(v0 - h0, v1 - h1);
}

// cp.async 16B
__device__ __forceinline__ void cpa16(uint32_t dst, const void* src) {
    asm volatile("cp.async.cg.shared.global [%0], [%1], 16;" :: "r"(dst), "l"(src) : "memory");
}
#define CP_COMMIT() asm volatile("cp.async.commit_group;" ::: "memory")
#define CP_WAIT1()  asm volatile("cp.async.wait_group 1;" ::: "memory")
#define CP_WAIT0()  asm volatile("cp.async.wait_group 0;" ::: "memory")

// async tile fetch: rows x 64 bf16 -> swizzled smem
__device__ __forceinline__ void cp_tile(uint32_t dst, const __nv_bfloat16* __restrict__ src,
                                        int ld, int tid, int rows) {
    int nchunk = rows * 8;
    for (int c = tid; c < nchunk; c += 256) {
        int r = c >> 3, g = c & 7;
        cpa16(dst + SWZ((uint32_t)(r * 128 + g * 16)), src + (size_t)r * ld + g * 8);
    }
}
// sync tile load (scores kernel)
__device__ __forceinline__ void load_b16(uint32_t dst, const __nv_bfloat16* __restrict__ src,
                                         int ld, int tid, int rows) {
    int nchunk = rows * 8;
    for (int c = tid; c < nchunk; c += 256) {
        int r = c >> 3, g = c & 7;
        uint4 v = *(const uint4*)(src + (size_t)r * ld + g * 8);
        sts128(dst + SWZ((uint32_t)(r * 128 + g * 16)), v);
    }
}

// A-prefetch for att: 128x64 fp32 chunk -> 32 regs/thread
__device__ __forceinline__ void loadA_regs(float* va, const float* __restrict__ src,
                                           int ld, int tid) {
#pragma unroll
    for (int it = 0; it < 4; it++) {
        int c = tid + it * 256;
        int r = c >> 3, g = c & 7;
        const float* p = src + (size_t)r * ld + g * 8;
        float4 f0 = *(const float4*)p;
        float4 f1 = *(const float4*)(p + 4);
        va[it * 8 + 0] = f0.x; va[it * 8 + 1] = f0.y; va[it * 8 + 2] = f0.z; va[it * 8 + 3] = f0.w;
        va[it * 8 + 4] = f1.x; va[it * 8 + 5] = f1.y; va[it * 8 + 6] = f1.z; va[it * 8 + 7] = f1.w;
    }
}
// convert regs -> split bf16 swizzled smem
__device__ __forceinline__ void storeA_split(uint32_t dhi, uint32_t dlo, const float* va, int tid) {
#pragma unroll
    for (int it = 0; it < 4; it++) {
        int c = tid + it * 256;
        int r = c >> 3, g = c & 7;
        uint4 H, L;
        uint32_t* Hp = (uint32_t*)&H;
        uint32_t* Lp = (uint32_t*)&L;
#pragma unroll
        for (int pp = 0; pp < 4; pp++) {
            float v0 = va[it * 8 + pp * 2], v1 = va[it * 8 + pp * 2 + 1];
            float h0 = __bfloat162float(__float2bfloat16(v0));
            float h1 = __bfloat162float(__float2bfloat16(v1));
            Hp[pp] = bpair(h0, h1);
            Lp[pp] = bpair(v0 - h0, v1 - h1);
        }
        uint32_t ad = SWZ((uint32_t)(r * 128 + g * 16));
        sts128(dhi + ad, H);
        sts128(dlo + ad, L);
    }
}

// smem stage layouts
#define PSTAGE 65536          // proj/out: AH 16K | AL 16K | BH 16K | BL 16K
#define SMEM_PIPE (2 * PSTAGE)
#define ASTAGE 49152          // att: AH 16K | AL 16K | BH 8K | BL 8K
#define SMEM_ATT (2 * ASTAGE)
#define SMEM_SCORES 65536

// ===========================================================================
// mma core on one stage: 128x128 tile, 8 warps (2x4), warp 64x32
// ===========================================================================
__device__ __forceinline__ void mma_chunk_128(float acc[4][4][4], uint32_t bs,
                                              int wm, int wn, int lane) {
#pragma unroll
    for (int ks = 0; ks < 4; ks++) {
        uint32_t ah[4][4], al[4][4], bh[4][2], bl[4][2];
        int acol = ks * 32 + (lane >> 4) * 16;
#pragma unroll
        for (int mi = 0; mi < 4; mi++) {
            int arow = wm * 64 + mi * 16 + (lane & 15);
            uint32_t off = SWZ((uint32_t)(arow * 128 + acol));
            ldmx4(ah[mi], bs + off);
            ldmx4(al[mi], bs + 16384 + off);
        }
        int bcol = ks * 32 + ((lane >> 3) & 1) * 16;
#pragma unroll
        for (int nj = 0; nj < 2; nj++) {
            int brow = wn * 32 + nj * 16 + (lane & 7) + (lane >> 4) * 8;
            uint32_t off = SWZ((uint32_t)(brow * 128 + bcol));
            uint32_t t[4];
            ldmx4(t, bs + 32768 + off);
            bh[nj * 2][0] = t[0]; bh[nj * 2][1] = t[1];
            bh[nj * 2 + 1][0] = t[2]; bh[nj * 2 + 1][1] = t[3];
            ldmx4(t, bs + 49152 + off);
            bl[nj * 2][0] = t[0]; bl[nj * 2][1] = t[1];
            bl[nj * 2 + 1][0] = t[2]; bl[nj * 2 + 1][1] = t[3];
        }
#pragma unroll
        for (int mi = 0; mi < 4; mi++)
#pragma unroll
            for (int ni = 0; ni < 4; ni++) {
                mma16816(acc[mi][ni], ah[mi], bh[ni]);
                mma16816(acc[mi][ni], ah[mi], bl[ni]);
                mma16816(acc[mi][ni], al[mi], bh[ni]);
            }
    }
}

// ---------------------------------------------------------------------------
// xsplit: q/k/v fp32 -> bf16 hi/lo. grid (2048, 3), block 256, 8 elems/thread
// ---------------------------------------------------------------------------
__global__ void __launch_bounds__(256) xsplit_kernel(
    const float* __restrict__ q, const float* __restrict__ k, const float* __restrict__ v)
{
    int z = blockIdx.y;
    const float* X = (z == 0) ? q : ((z == 1) ? k : v);
    size_t idx = ((size_t)blockIdx.x * 256 + threadIdx.x) * 8;
    float4 f0 = *(const float4*)(X + idx);
    float4 f1 = *(const float4*)(X + idx + 4);
    float val[8] = {f0.x, f0.y, f0.z, f0.w, f1.x, f1.y, f1.z, f1.w};
    uint4 H, L;
    uint32_t* Hp = (uint32_t*)&H;
    uint32_t* Lp = (uint32_t*)&L;
#pragma unroll
    for (int pp = 0; pp < 4; pp++) {
        float h0 = __bfloat162float(__float2bfloat16(val[pp * 2]));
        float h1 = __bfloat162float(__float2bfloat16(val[pp * 2 + 1]));
        Hp[pp] = bpair(h0, h1);
        Lp[pp] = bpair(val[pp * 2] - h0, val[pp * 2 + 1] - h1);
    }
    *(uint4*)(g_x_hi[z] + idx) = H;
    *(uint4*)(g_x_lo[z] + idx) = L;
}

// ---------------------------------------------------------------------------
// Weight transpose+split (unchanged)
// ---------------------------------------------------------------------------
__global__ void __launch_bounds__(256) wsplit_qkv(
    const float* __restrict__ wq, const float* __restrict__ wk, const float* __restrict__ wv)
{
    __shared__ float tile[32][33];
    int z = blockIdx.z >> 4, h = blockIdx.z & 15;
    const float* W = (z == 0) ? wq : ((z == 1) ? wk : wv);
    int d0 = blockIdx.x * 32, e0 = blockIdx.y * 32;
    int tx = threadIdx.x, ty = threadIdx.y;
#pragma unroll
    for (int i = 0; i < 4; i++) {
        int d = d0 + ty + i * 8;
        tile[ty + i * 8][tx] = W[(size_t)h * DN * EN + (size_t)d * EN + e0 + tx];
    }
    __syncthreads();
#pragma unroll
    for (int i = 0; i < 4; i++) {
        int e = e0 + ty + i * 8;
        int n = h * EN + e, k = d0 + tx;
        float v = tile[tx][ty + i * 8];
        float hf = __bfloat162float(__float2bfloat16(v));
        g_w_hi[z][(size_t)n * DN + k] = __float2bfloat16(hf);
        g_w_lo[z][(size_t)n * DN + k] = __float2bfloat16(v - hf);
    }
}

__global__ void __launch_bounds__(256) wsplit_o(const float* __restrict__ wo)
{
    __shared__ float tile[32][33];
    int k0 = blockIdx.x * 32, n0 = blockIdx.y * 32;
    int tx = threadIdx.x, ty = threadIdx.y;
#pragma unroll
    for (int i = 0; i < 4; i++)
        tile[ty + i * 8][tx] = wo[(size_t)(k0 + ty + i * 8) * DN + n0 + tx];
    __syncthreads();
#pragma unroll
    for (int i = 0; i < 4; i++) {
        int n = n0 + ty + i * 8, k = k0 + tx;
        float v = tile[tx][ty + i * 8];
        float hf = __bfloat162float(__float2bfloat16(v));
        g_w_hi[3][(size_t)n * DN + k] = __float2bfloat16(hf);
        g_w_lo[3][(size_t)n * DN + k] = __float2bfloat16(v - hf);
    }
}

__global__ void __launch_bounds__(256) vtrans_kernel()
{
    __shared__ __nv_bfloat16 th[32][33];
    __shared__ __nv_bfloat16 tl[32][33];
    int hb = blockIdx.z, h = hb >> 1, b = hb & 1;
    int s0 = blockIdx.x * 32, e0 = blockIdx.y * 32;
    int tx = threadIdx.x, ty = threadIdx.y;
#pragma unroll
    for (int i = 0; i < 4; i++) {
        size_t src = (size_t)(b * SN + s0 + ty + i * 8) * DN + h * EN + e0 + tx;
        th[ty + i * 8][tx] = g_p_hi[2][src];
        tl[ty + i * 8][tx] = g_p_lo[2][src];
    }
    __syncthreads();
#pragma unroll
    for (int i = 0; i < 4; i++) {
        int e = e0 + ty + i * 8;
        size_t dst = (size_t)e * SN + s0 + tx;
        g_vt_hi[hb][dst] = th[tx][ty + i * 8];
        g_vt_lo[hb][dst] = tl[tx][ty + i * 8];
    }
}

// ---------------------------------------------------------------------------
// Projection GEMM, cp.async double-buffered. grid (32, 8, 3)
// ---------------------------------------------------------------------------
__device__ __forceinline__ void issue4(uint32_t base,
    const __nv_bfloat16* ah, const __nv_bfloat16* al,
    const __nv_bfloat16* bh, const __nv_bfloat16* bl, int tid) {
    cp_tile(base,         ah, DN, tid, 128);
    cp_tile(base + 16384, al, DN, tid, 128);
    cp_tile(base + 32768, bh, DN, tid, 128);
    cp_tile(base + 49152, bl, DN, tid, 128);
}

__global__ void __launch_bounds__(256) gemm_proj(int dummy)
{
    extern __shared__ char smem[];
    uint32_t sb = smem_u32(smem);
    int tid = threadIdx.x, wid = tid >> 5, lane = tid & 31;
    int z = blockIdx.z;
    const __nv_bfloat16* Axh = g_x_hi[z];
    const __nv_bfloat16* Axl = g_x_lo[z];
    const __nv_bfloat16* Bhi = g_w_hi[z];
    const __nv_bfloat16* Blo = g_w_lo[z];
    __nv_bfloat16* Chi = g_p_hi[z];
    __nv_bfloat16* Clo = g_p_lo[z];
    int m0 = blockIdx.x * 128, n0 = blockIdx.y * 128;
    int wm = wid & 1, wn = wid >> 1;

    issue4(sb, Axh + (size_t)m0 * DN, Axl + (size_t)m0 * DN,
           Bhi + (size_t)n0 * DN, Blo + (size_t)n0 * DN, tid);
    CP_COMMIT();

    float acc[4][4][4] = {};
#pragma unroll 1
    for (int s = 0; s < 16; s++) {
        if (s < 15) {
            int kc = (s + 1) * 64;
            uint32_t nb = sb + ((s + 1) & 1) * PSTAGE;
            issue4(nb, Axh + (size_t)m0 * DN + kc, Axl + (size_t)m0 * DN + kc,
                   Bhi + (size_t)n0 * DN + kc, Blo + (size_t)n0 * DN + kc, tid);
            CP_COMMIT();
            CP_WAIT1();
        } else {
            CP_WAIT0();
        }
        __syncthreads();
        mma_chunk_128(acc, sb + (s & 1) * PSTAGE, wm, wn, lane);
        __syncthreads();
    }

    size_t rbase = (size_t)m0 + wm * 64;
    int cbase = n0 + wn * 32;
#pragma unroll
    for (int mi = 0; mi < 4; mi++)
#pragma unroll
        for (int ni = 0; ni < 4; ni++) {
            size_t r0 = rbase + mi * 16 + (lane >> 2);
            int c = cbase + ni * 8 + (lane & 3) * 2;
            store_split2(Chi, Clo, r0 * DN + c,       acc[mi][ni][0], acc[mi][ni][1]);
            store_split2(Chi, Clo, (r0 + 8) * DN + c, acc[mi][ni][2], acc[mi][ni][3]);
        }
}

// ---------------------------------------------------------------------------
// Scores GEMM (K=64, single chunk). grid (16,16,32) — latency hidden by grid.
// ---------------------------------------------------------------------------
__global__ void __launch_bounds__(256) gemm_scores(float* attn_arg)
{
    extern __shared__ char smem[];
    uint32_t sb = smem_u32(smem);
    int tid = threadIdx.x, wid = tid >> 5, lane = tid & 31;
    float* attn = attn_arg ? attn_arg : g_attn_fb;
    int hb = blockIdx.z, h = hb >> 1, b = hb & 1;
    int m0 = blockIdx.x * 128, n0 = blockIdx.y * 128;
    const __nv_bfloat16* Ah = g_p_hi[0] + (size_t)(b * SN + m0) * DN + h * EN;
    const __nv_bfloat16* Al = g_p_lo[0] + (size_t)(b * SN + m0) * DN + h * EN;
    const __nv_bfloat16* Bh = g_p_hi[1] + (size_t)(b * SN + n0) * DN + h * EN;
    const __nv_bfloat16* Bl = g_p_lo[1] + (size_t)(b * SN + n0) * DN + h * EN;
    float* C = attn + (size_t)hb * SN * SN;
    int wm = wid & 1, wn = wid >> 1;

    load_b16(sb,         Ah, DN, tid, 128);
    load_b16(sb + 16384, Al, DN, tid, 128);
    load_b16(sb + 32768, Bh, DN, tid, 128);
    load_b16(sb + 49152, Bl, DN, tid, 128);
    __syncthreads();

    float acc[4][4][4] = {};
    mma_chunk_128(acc, sb, wm, wn, lane);

    const float sc = 1.0f / 64.0f;
    size_t rbase = (size_t)m0 + wm * 64;
    int cbase = n0 + wn * 32;
#pragma unroll
    for (int mi = 0; mi < 4; mi++)
#pragma unroll
        for (int ni = 0; ni < 4; ni++) {
            size_t r0 = rbase + mi * 16 + (lane >> 2);
            int c = cbase + ni * 8 + (lane & 3) * 2;
            *(float2*)(C + r0 * SN + c)       = make_float2(acc[mi][ni][0] * sc, acc[mi][ni][1] * sc);
            *(float2*)(C + (r0 + 8) * SN + c) = make_float2(acc[mi][ni][2] * sc, acc[mi][ni][3] * sc);
        }
}

// ---------------------------------------------------------------------------
// Row softmax (unchanged)
// ---------------------------------------------------------------------------
__global__ void __launch_bounds__(256) softmax_kernel(float* attn_arg)
{
    float* attn = attn_arg ? attn_arg : g_attn_fb;
    size_t row = blockIdx.x;
    float* p = attn + row * (size_t)SN;
    int tid = threadIdx.x;

    float4 v0 = *(float4*)(p + tid * 8);
    float4 v1 = *(float4*)(p + tid * 8 + 4);

    float m = fmaxf(fmaxf(fmaxf(v0.x, v0.y), fmaxf(v0.z, v0.w)),
                    fmaxf(fmaxf(v1.x, v1.y), fmaxf(v1.z, v1.w)));
    __shared__ float sm[8];
#pragma unroll
    for (int o = 16; o > 0; o >>= 1) m = fmaxf(m, __shfl_xor_sync(0xffffffffu, m, o));
    if ((tid & 31) == 0) sm[tid >> 5] = m;
    __syncthreads();
    if (tid < 32) {
        float t = (tid < 8) ? sm[tid] : -3.0e38f;
#pragma unroll
        for (int o = 4; o > 0; o >>= 1) t = fmaxf(t, __shfl_xor_sync(0xffffffffu, t, o));
        if (tid == 0) sm[0] = t;
    }
    __syncthreads();
    m = sm[0];
    __syncthreads();

    float e0 = __expf(v0.x - m), e1 = __expf(v0.y - m), e2 = __expf(v0.z - m), e3 = __expf(v0.w - m);
    float e4 = __expf(v1.x - m), e5 = __expf(v1.y - m), e6 = __expf(v1.z - m), e7 = __expf(v1.w - m);
    float s = ((e0 + e1) + (e2 + e3)) + ((e4 + e5) + (e6 + e7));
#pragma unroll
    for (int o = 16; o > 0; o >>= 1) s += __shfl_xor_sync(0xffffffffu, s, o);
    if ((tid & 31) == 0) sm[tid >> 5] = s;
    __syncthreads();
    if (tid < 32) {
        float t = (tid < 8) ? sm[tid] : 0.0f;
#pragma unroll
        for (int o = 4; o > 0; o >>= 1) t += __shfl_xor_sync(0xffffffffu, t, o);
        if (tid == 0) sm[0] = t;
    }
    __syncthreads();
    float inv = 1.0f / sm[0];

    *(float4*)(p + tid * 8)     = make_float4(e0 * inv, e1 * inv, e2 * inv, e3 * inv);
    *(float4*)(p + tid * 8 + 4) = make_float4(e4 * inv, e5 * inv, e6 * inv, e7 * inv);
}

// ---------------------------------------------------------------------------
// att GEMM: pipelined. A regs-prefetch + convert; B cp.async. grid (16,1,32)
// ---------------------------------------------------------------------------
__global__ void __launch_bounds__(256) gemm_att(const float* attn_arg)
{
    extern __shared__ char smem[];
    uint32_t sb = smem_u32(smem);
    int tid = threadIdx.x, wid = tid >> 5, lane = tid & 31;
    const float* attn = attn_arg ? attn_arg : g_attn_fb;
    int hb = blockIdx.z, h = hb >> 1, b = hb & 1;
    int m0 = blockIdx.x * 128;
    const float* A = attn + (size_t)hb * SN * SN + (size_t)m0 * SN;
    int wm = wid & 3, wn = wid >> 2;

    float va[32];
    loadA_regs(va, A, SN, tid);
    cp_tile(sb + 32768, g_vt_hi[hb], SN, tid, 64);
    cp_tile(sb + 40960, g_vt_lo[hb], SN, tid, 64);
    CP_COMMIT();

    float acc[2][4][4] = {};
#pragma unroll 1
    for (int s = 0; s < 32; s++) {
        uint32_t bs = sb + (s & 1) * ASTAGE;
        storeA_split(bs, bs + 16384, va, tid);
        if (s < 31) {
            int kc = (s + 1) * 64;
            uint32_t nb = sb + ((s + 1) & 1) * ASTAGE;
            cp_tile(nb + 32768, g_vt_hi[hb] + kc, SN, tid, 64);
            cp_tile(nb + 40960, g_vt_lo[hb] + kc, SN, tid, 64);
            CP_COMMIT();
            CP_WAIT1();
        } else {
            CP_WAIT0();
        }
        __syncthreads();
        if (s < 31) loadA_regs(va, A + (s + 1) * 64, SN, tid);
#pragma unroll
        for (int ks = 0; ks < 4; ks++) {
            uint32_t ah[2][4], al[2][4], bh[4][2], bl[4][2];
            int acol = ks * 32 + (lane >> 4) * 16;
#pragma unroll
            for (int mi = 0; mi < 2; mi++) {
                int arow = wm * 32 + mi * 16 + (lane & 15);
                uint32_t off = SWZ((uint32_t)(arow * 128 + acol));
                ldmx4(ah[mi], bs + off);
                ldmx4(al[mi], bs + 16384 + off);
            }
            int bcol = ks * 32 + ((lane >> 3) & 1) * 16;
#pragma unroll
            for (int nj = 0; nj < 2; nj++) {
                int brow = wn * 32 + nj * 16 + (lane & 7) + (lane >> 4) * 8;
                uint32_t off = SWZ((uint32_t)(brow * 128 + bcol));
                uint32_t t[4];
                ldmx4(t, bs + 32768 + off);
                bh[nj * 2][0] = t[0]; bh[nj * 2][1] = t[1];
                bh[nj * 2 + 1][0] = t[2]; bh[nj * 2 + 1][1] = t[3];
                ldmx4(t, bs + 40960 + off);
                bl[nj * 2][0] = t[0]; bl[nj * 2][1] = t[1];
                bl[nj * 2 + 1][0] = t[2]; bl[nj * 2 + 1][1] = t[3];
            }
#pragma unroll
            for (int mi = 0; mi < 2; mi++)
#pragma unroll
                for (int ni = 0; ni < 4; ni++) {
                    mma16816(acc[mi][ni], ah[mi], bh[ni]);
                    mma16816(acc[mi][ni], ah[mi], bl[ni]);
                    mma16816(acc[mi][ni], al[mi], bh[ni]);
                }
        }
        __syncthreads();
    }

    size_t rbase = (size_t)(b * SN + m0) + wm * 32;
    int cbase = h * EN + wn * 32;
#pragma unroll
    for (int mi = 0; mi < 2; mi++)
#pragma unroll
        for (int ni = 0; ni < 4; ni++) {
            size_t r0 = rbase + mi * 16 + (lane >> 2);
            int c = cbase + ni * 8 + (lane & 3) * 2;
            store_split2(g_cat_hi, g_cat_lo, r0 * DN + c,       acc[mi][ni][0], acc[mi][ni][1]);
            store_split2(g_cat_hi, g_cat_lo, (r0 + 8) * DN + c, acc[mi][ni][2], acc[mi][ni][3]);
        }
}

// ---------------------------------------------------------------------------
// Output GEMM, cp.async double-buffered. grid (32, 8)
// ---------------------------------------------------------------------------
__global__ void __launch_bounds__(256) gemm_out(float* __restrict__ out)
{
    extern __shared__ char smem[];
    uint32_t sb = smem_u32(smem);
    int tid = threadIdx.x, wid = tid >> 5, lane = tid & 31;
    int m0 = blockIdx.x * 128, n0 = blockIdx.y * 128;
    int wm = wid & 1, wn = wid >> 1;

    issue4(sb, g_cat_hi + (size_t)m0 * DN, g_cat_lo + (size_t)m0 * DN,
           g_w_hi[3] + (size_t)n0 * DN, g_w_lo[3] + (size_t)n0 * DN, tid);
    CP_COMMIT();

    float acc[4][4][4] = {};
#pragma unroll 1
    for (int s = 0; s < 16; s++) {
        if (s < 15) {
            int kc = (s + 1) * 64;
            uint32_t nb = sb + ((s + 1) & 1) * PSTAGE;
            issue4(nb, g_cat_hi + (size_t)m0 * DN + kc, g_cat_lo + (size_t)m0 * DN + kc,
                   g_w_hi[3] + (size_t)n0 * DN + kc, g_w_lo[3] + (size_t)n0 * DN + kc, tid);
            CP_COMMIT();
            CP_WAIT1();
        } else {
            CP_WAIT0();
        }
        __syncthreads();
        mma_chunk_128(acc, sb + (s & 1) * PSTAGE, wm, wn, lane);
        __syncthreads();
    }

    size_t rbase = (size_t)m0 + wm * 64;
    int cbase = n0 + wn * 32;
#pragma unroll
    for (int mi = 0; mi < 4; mi++)
#pragma unroll
        for (int ni = 0; ni < 4; ni++) {
            size_t r0 = rbase + mi * 16 + (lane >> 2);
            int c = cbase + ni * 8 + (lane & 3) * 2;
            *(float2*)(out + r0 * DN + c)       = make_float2(acc[mi][ni][0], acc[mi][ni][1]);
            *(float2*)(out + (r0 + 8) * DN + c) = make_float2(acc[mi][ni][2], acc[mi][ni][3]);
        }
}

// ---------------------------------------------------------------------------
extern "C" void kernel_launch(void* const* d_in, const int* in_sizes, int n_in,
                              void* d_out, int out_size)
{
    const float* acts[3] = {nullptr, nullptr, nullptr};
    const float* wts[4]  = {nullptr, nullptr, nullptr, nullptr};
    int na = 0, nw = 0;
    for (int i = 0; i < n_in; i++) {
        if (in_sizes[i] == BSN * DN && na < 3) acts[na++] = (const float*)d_in[i];
        else if (nw < 4)                       wts[nw++]  = (const float*)d_in[i];
    }
    if (na != 3 || nw != 4) {
        acts[0] = (const float*)d_in[0]; acts[1] = (const float*)d_in[1]; acts[2] = (const float*)d_in[2];
        wts[0]  = (const float*)d_in[3]; wts[1]  = (const float*)d_in[4];
        wts[2]  = (const float*)d_in[5]; wts[3]  = (const float*)d_in[6];
    }
    const float* q  = acts[0];
    const float* k  = acts[1];
    const float* v  = acts[2];
    const float* Wq = wts[0];
    const float* Wk = wts[1];
    const float* Wv = wts[2];
    const float* Wo = wts[3];
    float* out = (float*)d_out;

    const long long OUT_E  = (long long)BSN * DN;
    const long long ATTN_E = (long long)HBN * SN * SN;
    float* attn_ptr = ((long long)out_size >= OUT_E + ATTN_E) ? (out + OUT_E) : nullptr;

    cudaFuncSetAttribute(gemm_proj,   cudaFuncAttributeMaxDynamicSharedMemorySize, SMEM_PIPE);
    cudaFuncSetAttribute(gemm_scores, cudaFuncAttributeMaxDynamicSharedMemorySize, SMEM_SCORES);
    cudaFuncSetAttribute(gemm_att,    cudaFuncAttributeMaxDynamicSharedMemorySize, SMEM_ATT);
    cudaFuncSetAttribute(gemm_out,    cudaFuncAttributeMaxDynamicSharedMemorySize, SMEM_PIPE);

    xsplit_kernel<<<dim3(2048, 3), 256>>>(q, k, v);
    wsplit_qkv<<<dim3(32, 2, 48), dim3(32, 8)>>>(Wq, Wk, Wv);
    wsplit_o<<<dim3(32, 32), dim3(32, 8)>>>(Wo);
    gemm_proj<<<dim3(32, 8, 3), 256, SMEM_PIPE>>>(0);
    vtrans_kernel<<<dim3(64, 2, 32), dim3(32, 8)>>>();
    gemm_scores<<<dim3(16, 16, 32), 256, SMEM_SCORES>>>(attn_ptr);
    softmax_kernel<<<dim3(HBN * SN), 256>>>(attn_ptr);
    gemm_att<<<dim3(16, 1, 32), 256, SMEM_ATT>>>(attn_ptr);
    gemm_out<<<dim3(32, 8), 256, SMEM_PIPE>>>(out);
}

// round 10
// speedup vs baseline: 1.9731x; 1.0172x over previous
#include <cuda_runtime.h>
#include <cuda_bf16.h>
#include <cstdint>

#define HN 16
#define BN_ 2
#define SN 2048
#define DN 1024
#define EN 64
#define BSN 4096
#define HBN 32

// ---------------- device scratch (allocation-free rule) ----------------
__device__ __align__(256) __nv_bfloat16 g_w_hi[4][DN * DN];   // [z][n][k]
__device__ __align__(256) __nv_bfloat16 g_w_lo[4][DN * DN];
__device__ __align__(256) __nv_bfloat16 g_x_hi[3][BSN * DN];  // q/k/v split [b*S+s][d]
__device__ __align__(256) __nv_bfloat16 g_x_lo[3][BSN * DN];
__device__ __align__(256) __nv_bfloat16 g_p_hi[3][BSN * DN];  // qh/kh/vh split
__device__ __align__(256) __nv_bfloat16 g_p_lo[3][BSN * DN];
__device__ __align__(256) __nv_bfloat16 g_vt_hi[HBN][EN * SN]; // V^T per head
__device__ __align__(256) __nv_bfloat16 g_vt_lo[HBN][EN * SN];
__device__ __align__(256) __nv_bfloat16 g_cat_hi[BSN * DN];
__device__ __align__(256) __nv_bfloat16 g_cat_lo[BSN * DN];
__device__ __align__(256) float g_attn_fb[(size_t)HBN * SN * SN];

// ---------------- helpers ----------------
__device__ __forceinline__ uint32_t smem_u32(const void* p) {
    uint32_t a;
    asm("{ .reg .u64 t; cvta.to.shared.u64 t, %1; cvt.u32.u64 %0, t; }" : "=r"(a) : "l"(p));
    return a;
}
#define SWZ(x) ((x) ^ (((x) >> 3) & 0x70))

__device__ __forceinline__ void sts128(uint32_t addr, uint4 v) {
    asm volatile("st.shared.v4.b32 [%0], {%1,%2,%3,%4};"
                 :: "r"(addr), "r"(v.x), "r"(v.y), "r"(v.z), "r"(v.w) : "memory");
}
__device__ __forceinline__ uint32_t bpair(float a, float b) {
    uint32_t r;
    asm("cvt.rn.bf16x2.f32 %0, %1, %2;" : "=r"(r) : "f"(b), "f"(a));
    return r;
}
__device__ __forceinline__ void ldmx4(uint32_t* r, uint32_t addr) {
    asm volatile("ldmatrix.sync.aligned.m8n8.x4.shared.b16 {%0,%1,%2,%3}, [%4];"
                 : "=r"(r[0]), "=r"(r[1]), "=r"(r[2]), "=r"(r[3]) : "r"(addr));
}
__device__ __forceinline__ void mma16816(float* d, const uint32_t* a, const uint32_t* b) {
    asm volatile("mma.sync.aligned.m16n8k16.row.col.f32.bf16.bf16.f32 "
        "{%0,%1,%2,%3}, {%4,%5,%6,%7}, {%8,%9}, {%0,%1,%2,%3};"
        : "+f"(d[0]), "+f"(d[1]), "+f"(d[2]), "+f"(d[3])
        : "r"(a[0]), "r"(a[1]), "r"(a[2]), "r"(a[3]), "r"(b[0]), "r"(b[1]));
}
__device__ __forceinline__ void store_split2(__nv_bfloat16* Chi, __nv_bfloat16* Clo,
                                             size_t off, float v0, float v1) {
    float h0 = __bfloat162float(__float2bfloat16(v0));
    float h1 = __bfloat162float(__float2bfloat16(v1));
    *(uint32_t*)(Chi + off) = bpair(h0, h1);
    *(uint32_t*)(Clo + off) = bpair(v0 - h0, v1 - h1);
}

// cp.async 16B
__device__ __forceinline__ void cpa16(uint32_t dst, const void* src) {
    asm volatile("cp.async.cg.shared.global [%0], [%1], 16;" :: "r"(dst), "l"(src) : "memory");
}
#define CP_COMMIT() asm volatile("cp.async.commit_group;" ::: "memory")
#define CP_WAIT1()  asm volatile("cp.async.wait_group 1;" ::: "memory")
#define CP_WAIT0()  asm volatile("cp.async.wait_group 0;" ::: "memory")

__device__ __forceinline__ void cp_tile(uint32_t dst, const __nv_bfloat16* __restrict__ src,
                                        int ld, int tid, int rows) {
    int nchunk = rows * 8;
    for (int c = tid; c < nchunk; c += 256) {
        int r = c >> 3, g = c & 7;
        cpa16(dst + SWZ((uint32_t)(r * 128 + g * 16)), src + (size_t)r * ld + g * 8);
    }
}
__device__ __forceinline__ void load_b16(uint32_t dst, const __nv_bfloat16* __restrict__ src,
                                         int ld, int tid, int rows) {
    int nchunk = rows * 8;
    for (int c = tid; c < nchunk; c += 256) {
        int r = c >> 3, g = c & 7;
        uint4 v = *(const uint4*)(src + (size_t)r * ld + g * 8);
        sts128(dst + SWZ((uint32_t)(r * 128 + g * 16)), v);
    }
}

// A-prefetch for att: 128x64 fp32 chunk -> 32 regs/thread
__device__ __forceinline__ void loadA_regs(float* va, const float* __restrict__ src,
                                           int ld, int tid) {
#pragma unroll
    for (int it = 0; it < 4; it++) {
        int c = tid + it * 256;
        int r = c >> 3, g = c & 7;
        const float* p = src + (size_t)r * ld + g * 8;
        float4 f0 = *(const float4*)p;
        float4 f1 = *(const float4*)(p + 4);
        va[it * 8 + 0] = f0.x; va[it * 8 + 1] = f0.y; va[it * 8 + 2] = f0.z; va[it * 8 + 3] = f0.w;
        va[it * 8 + 4] = f1.x; va[it * 8 + 5] = f1.y; va[it * 8 + 6] = f1.z; va[it * 8 + 7] = f1.w;
    }
}
__device__ __forceinline__ void storeA_split(uint32_t dhi, uint32_t dlo, const float* va, int tid) {
#pragma unroll
    for (int it = 0; it < 4; it++) {
        int c = tid + it * 256;
        int r = c >> 3, g = c & 7;
        uint4 H, L;
        uint32_t* Hp = (uint32_t*)&H;
        uint32_t* Lp = (uint32_t*)&L;
#pragma unroll
        for (int pp = 0; pp < 4; pp++) {
            float v0 = va[it * 8 + pp * 2], v1 = va[it * 8 + pp * 2 + 1];
            float h0 = __bfloat162float(__float2bfloat16(v0));
            float h1 = __bfloat162float(__float2bfloat16(v1));
            Hp[pp] = bpair(h0, h1);
            Lp[pp] = bpair(v0 - h0, v1 - h1);
        }
        uint32_t ad = SWZ((uint32_t)(r * 128 + g * 16));
        sts128(dhi + ad, H);
        sts128(dlo + ad, L);
    }
}

// smem stage layouts: 3-stage rings
#define PSTAGE 65536          // proj/out: AH 16K | AL 16K | BH 16K | BL 16K
#define SMEM_PIPE (3 * PSTAGE)   // 192 KB
#define ASTAGE 49152          // att: AH 16K | AL 16K | BH 8K | BL 8K
#define SMEM_ATT (3 * ASTAGE)    // 144 KB
#define SMEM_SCORES 65536

// ===========================================================================
// mma core on one stage: 128x128 tile, 8 warps (2x4), warp 64x32
// ===========================================================================
__device__ __forceinline__ void mma_chunk_128(float acc[4][4][4], uint32_t bs,
                                              int wm, int wn, int lane) {
#pragma unroll
    for (int ks = 0; ks < 4; ks++) {
        uint32_t ah[4][4], al[4][4], bh[4][2], bl[4][2];
        int acol = ks * 32 + (lane >> 4) * 16;
#pragma unroll
        for (int mi = 0; mi < 4; mi++) {
            int arow = wm * 64 + mi * 16 + (lane & 15);
            uint32_t off = SWZ((uint32_t)(arow * 128 + acol));
            ldmx4(ah[mi], bs + off);
            ldmx4(al[mi], bs + 16384 + off);
        }
        int bcol = ks * 32 + ((lane >> 3) & 1) * 16;
#pragma unroll
        for (int nj = 0; nj < 2; nj++) {
            int brow = wn * 32 + nj * 16 + (lane & 7) + (lane >> 4) * 8;
            uint32_t off = SWZ((uint32_t)(brow * 128 + bcol));
            uint32_t t[4];
            ldmx4(t, bs + 32768 + off);
            bh[nj * 2][0] = t[0]; bh[nj * 2][1] = t[1];
            bh[nj * 2 + 1][0] = t[2]; bh[nj * 2 + 1][1] = t[3];
            ldmx4(t, bs + 49152 + off);
            bl[nj * 2][0] = t[0]; bl[nj * 2][1] = t[1];
            bl[nj * 2 + 1][0] = t[2]; bl[nj * 2 + 1][1] = t[3];
        }
#pragma unroll
        for (int mi = 0; mi < 4; mi++)
#pragma unroll
            for (int ni = 0; ni < 4; ni++) {
                mma16816(acc[mi][ni], ah[mi], bh[ni]);
                mma16816(acc[mi][ni], ah[mi], bl[ni]);
                mma16816(acc[mi][ni], al[mi], bh[ni]);
            }
    }
}

// ---------------------------------------------------------------------------
// xsplit: q/k/v fp32 -> bf16 hi/lo. grid (2048, 3)
// ---------------------------------------------------------------------------
__global__ void __launch_bounds__(256) xsplit_kernel(
    const float* __restrict__ q, const float* __restrict__ k, const float* __restrict__ v)
{
    int z = blockIdx.y;
    const float* X = (z == 0) ? q : ((z == 1) ? k : v);
    size_t idx = ((size_t)blockIdx.x * 256 + threadIdx.x) * 8;
    float4 f0 = *(const float4*)(X + idx);
    float4 f1 = *(const float4*)(X + idx + 4);
    float val[8] = {f0.x, f0.y, f0.z, f0.w, f1.x, f1.y, f1.z, f1.w};
    uint4 H, L;
    uint32_t* Hp = (uint32_t*)&H;
    uint32_t* Lp = (uint32_t*)&L;
#pragma unroll
    for (int pp = 0; pp < 4; pp++) {
        float h0 = __bfloat162float(__float2bfloat16(val[pp * 2]));
        float h1 = __bfloat162float(__float2bfloat16(val[pp * 2 + 1]));
        Hp[pp] = bpair(h0, h1);
        Lp[pp] = bpair(val[pp * 2] - h0, val[pp * 2 + 1] - h1);
    }
    *(uint4*)(g_x_hi[z] + idx) = H;
    *(uint4*)(g_x_lo[z] + idx) = L;
}

// ---------------------------------------------------------------------------
// Weight transpose+split (unchanged)
// ---------------------------------------------------------------------------
__global__ void __launch_bounds__(256) wsplit_qkv(
    const float* __restrict__ wq, const float* __restrict__ wk, const float* __restrict__ wv)
{
    __shared__ float tile[32][33];
    int z = blockIdx.z >> 4, h = blockIdx.z & 15;
    const float* W = (z == 0) ? wq : ((z == 1) ? wk : wv);
    int d0 = blockIdx.x * 32, e0 = blockIdx.y * 32;
    int tx = threadIdx.x, ty = threadIdx.y;
#pragma unroll
    for (int i = 0; i < 4; i++) {
        int d = d0 + ty + i * 8;
        tile[ty + i * 8][tx] = W[(size_t)h * DN * EN + (size_t)d * EN + e0 + tx];
    }
    __syncthreads();
#pragma unroll
    for (int i = 0; i < 4; i++) {
        int e = e0 + ty + i * 8;
        int n = h * EN + e, k = d0 + tx;
        float v = tile[tx][ty + i * 8];
        float hf = __bfloat162float(__float2bfloat16(v));
        g_w_hi[z][(size_t)n * DN + k] = __float2bfloat16(hf);
        g_w_lo[z][(size_t)n * DN + k] = __float2bfloat16(v - hf);
    }
}

__global__ void __launch_bounds__(256) wsplit_o(const float* __restrict__ wo)
{
    __shared__ float tile[32][33];
    int k0 = blockIdx.x * 32, n0 = blockIdx.y * 32;
    int tx = threadIdx.x, ty = threadIdx.y;
#pragma unroll
    for (int i = 0; i < 4; i++)
        tile[ty + i * 8][tx] = wo[(size_t)(k0 + ty + i * 8) * DN + n0 + tx];
    __syncthreads();
#pragma unroll
    for (int i = 0; i < 4; i++) {
        int n = n0 + ty + i * 8, k = k0 + tx;
        float v = tile[tx][ty + i * 8];
        float hf = __bfloat162float(__float2bfloat16(v));
        g_w_hi[3][(size_t)n * DN + k] = __float2bfloat16(hf);
        g_w_lo[3][(size_t)n * DN + k] = __float2bfloat16(v - hf);
    }
}

__global__ void __launch_bounds__(256) vtrans_kernel()
{
    __shared__ __nv_bfloat16 th[32][33];
    __shared__ __nv_bfloat16 tl[32][33];
    int hb = blockIdx.z, h = hb >> 1, b = hb & 1;
    int s0 = blockIdx.x * 32, e0 = blockIdx.y * 32;
    int tx = threadIdx.x, ty = threadIdx.y;
#pragma unroll
    for (int i = 0; i < 4; i++) {
        size_t src = (size_t)(b * SN + s0 + ty + i * 8) * DN + h * EN + e0 + tx;
        th[ty + i * 8][tx] = g_p_hi[2][src];
        tl[ty + i * 8][tx] = g_p_lo[2][src];
    }
    __syncthreads();
#pragma unroll
    for (int i = 0; i < 4; i++) {
        int e = e0 + ty + i * 8;
        size_t dst = (size_t)e * SN + s0 + tx;
        g_vt_hi[hb][dst] = th[tx][ty + i * 8];
        g_vt_lo[hb][dst] = tl[tx][ty + i * 8];
    }
}

// ---------------------------------------------------------------------------
// Projection GEMM: 3-stage cp.async ring, ONE barrier per chunk. grid (32,8,3)
// ---------------------------------------------------------------------------
__device__ __forceinline__ void issue4(uint32_t base,
    const __nv_bfloat16* ah, const __nv_bfloat16* al,
    const __nv_bfloat16* bh, const __nv_bfloat16* bl, int tid) {
    cp_tile(base,         ah, DN, tid, 128);
    cp_tile(base + 16384, al, DN, tid, 128);
    cp_tile(base + 32768, bh, DN, tid, 128);
    cp_tile(base + 49152, bl, DN, tid, 128);
}

__global__ void __launch_bounds__(256) gemm_proj(int dummy)
{
    extern __shared__ char smem[];
    uint32_t sb = smem_u32(smem);
    int tid = threadIdx.x, wid = tid >> 5, lane = tid & 31;
    int z = blockIdx.z;
    const __nv_bfloat16* Axh = g_x_hi[z];
    const __nv_bfloat16* Axl = g_x_lo[z];
    const __nv_bfloat16* Bhi = g_w_hi[z];
    const __nv_bfloat16* Blo = g_w_lo[z];
    __nv_bfloat16* Chi = g_p_hi[z];
    __nv_bfloat16* Clo = g_p_lo[z];
    int m0 = blockIdx.x * 128, n0 = blockIdx.y * 128;
    int wm = wid & 1, wn = wid >> 1;

    issue4(sb, Axh + (size_t)m0 * DN, Axl + (size_t)m0 * DN,
           Bhi + (size_t)n0 * DN, Blo + (size_t)n0 * DN, tid);
    CP_COMMIT();

    float acc[4][4][4] = {};
    int cur = 0, nxt = 1;
#pragma unroll 1
    for (int s = 0; s < 16; s++) {
        if (s < 15) {
            int kc = (s + 1) * 64;
            issue4(sb + nxt * PSTAGE, Axh + (size_t)m0 * DN + kc, Axl + (size_t)m0 * DN + kc,
                   Bhi + (size_t)n0 * DN + kc, Blo + (size_t)n0 * DN + kc, tid);
            CP_COMMIT();
            CP_WAIT1();
        } else {
            CP_WAIT0();
        }
        __syncthreads();   // single barrier: stage `cur` visible; ring distance 3 protects reuse
        mma_chunk_128(acc, sb + cur * PSTAGE, wm, wn, lane);
        cur = nxt; nxt = (nxt == 2) ? 0 : nxt + 1;
    }

    size_t rbase = (size_t)m0 + wm * 64;
    int cbase = n0 + wn * 32;
#pragma unroll
    for (int mi = 0; mi < 4; mi++)
#pragma unroll
        for (int ni = 0; ni < 4; ni++) {
            size_t r0 = rbase + mi * 16 + (lane >> 2);
            int c = cbase + ni * 8 + (lane & 3) * 2;
            store_split2(Chi, Clo, r0 * DN + c,       acc[mi][ni][0], acc[mi][ni][1]);
            store_split2(Chi, Clo, (r0 + 8) * DN + c, acc[mi][ni][2], acc[mi][ni][3]);
        }
}

// ---------------------------------------------------------------------------
// Scores GEMM (K=64, single chunk). grid (16,16,32)
// ---------------------------------------------------------------------------
__global__ void __launch_bounds__(256) gemm_scores(float* attn_arg)
{
    extern __shared__ char smem[];
    uint32_t sb = smem_u32(smem);
    int tid = threadIdx.x, wid = tid >> 5, lane = tid & 31;
    float* attn = attn_arg ? attn_arg : g_attn_fb;
    int hb = blockIdx.z, h = hb >> 1, b = hb & 1;
    int m0 = blockIdx.x * 128, n0 = blockIdx.y * 128;
    const __nv_bfloat16* Ah = g_p_hi[0] + (size_t)(b * SN + m0) * DN + h * EN;
    const __nv_bfloat16* Al = g_p_lo[0] + (size_t)(b * SN + m0) * DN + h * EN;
    const __nv_bfloat16* Bh = g_p_hi[1] + (size_t)(b * SN + n0) * DN + h * EN;
    const __nv_bfloat16* Bl = g_p_lo[1] + (size_t)(b * SN + n0) * DN + h * EN;
    float* C = attn + (size_t)hb * SN * SN;
    int wm = wid & 1, wn = wid >> 1;

    load_b16(sb,         Ah, DN, tid, 128);
    load_b16(sb + 16384, Al, DN, tid, 128);
    load_b16(sb + 32768, Bh, DN, tid, 128);
    load_b16(sb + 49152, Bl, DN, tid, 128);
    __syncthreads();

    float acc[4][4][4] = {};
    mma_chunk_128(acc, sb, wm, wn, lane);

    const float sc = 1.0f / 64.0f;
    size_t rbase = (size_t)m0 + wm * 64;
    int cbase = n0 + wn * 32;
#pragma unroll
    for (int mi = 0; mi < 4; mi++)
#pragma unroll
        for (int ni = 0; ni < 4; ni++) {
            size_t r0 = rbase + mi * 16 + (lane >> 2);
            int c = cbase + ni * 8 + (lane & 3) * 2;
            *(float2*)(C + r0 * SN + c)       = make_float2(acc[mi][ni][0] * sc, acc[mi][ni][1] * sc);
            *(float2*)(C + (r0 + 8) * SN + c) = make_float2(acc[mi][ni][2] * sc, acc[mi][ni][3] * sc);
        }
}

// ---------------------------------------------------------------------------
// Row softmax (unchanged)
// ---------------------------------------------------------------------------
__global__ void __launch_bounds__(256) softmax_kernel(float* attn_arg)
{
    float* attn = attn_arg ? attn_arg : g_attn_fb;
    size_t row = blockIdx.x;
    float* p = attn + row * (size_t)SN;
    int tid = threadIdx.x;

    float4 v0 = *(float4*)(p + tid * 8);
    float4 v1 = *(float4*)(p + tid * 8 + 4);

    float m = fmaxf(fmaxf(fmaxf(v0.x, v0.y), fmaxf(v0.z, v0.w)),
                    fmaxf(fmaxf(v1.x, v1.y), fmaxf(v1.z, v1.w)));
    __shared__ float sm[8];
#pragma unroll
    for (int o = 16; o > 0; o >>= 1) m = fmaxf(m, __shfl_xor_sync(0xffffffffu, m, o));
    if ((tid & 31) == 0) sm[tid >> 5] = m;
    __syncthreads();
    if (tid < 32) {
        float t = (tid < 8) ? sm[tid] : -3.0e38f;
#pragma unroll
        for (int o = 4; o > 0; o >>= 1) t = fmaxf(t, __shfl_xor_sync(0xffffffffu, t, o));
        if (tid == 0) sm[0] = t;
    }
    __syncthreads();
    m = sm[0];
    __syncthreads();

    float e0 = __expf(v0.x - m), e1 = __expf(v0.y - m), e2 = __expf(v0.z - m), e3 = __expf(v0.w - m);
    float e4 = __expf(v1.x - m), e5 = __expf(v1.y - m), e6 = __expf(v1.z - m), e7 = __expf(v1.w - m);
    float s = ((e0 + e1) + (e2 + e3)) + ((e4 + e5) + (e6 + e7));
#pragma unroll
    for (int o = 16; o > 0; o >>= 1) s += __shfl_xor_sync(0xffffffffu, s, o);
    if ((tid & 31) == 0) sm[tid >> 5] = s;
    __syncthreads();
    if (tid < 32) {
        float t = (tid < 8) ? sm[tid] : 0.0f;
#pragma unroll
        for (int o = 4; o > 0; o >>= 1) t += __shfl_xor_sync(0xffffffffu, t, o);
        if (tid == 0) sm[0] = t;
    }
    __syncthreads();
    float inv = 1.0f / sm[0];

    *(float4*)(p + tid * 8)     = make_float4(e0 * inv, e1 * inv, e2 * inv, e3 * inv);
    *(float4*)(p + tid * 8 + 4) = make_float4(e4 * inv, e5 * inv, e6 * inv, e7 * inv);
}

// ---------------------------------------------------------------------------
// att GEMM: 3-stage ring, single barrier per chunk. A via reg-prefetch+convert,
// B via cp.async. grid (16,1,32)
// ---------------------------------------------------------------------------
__global__ void __launch_bounds__(256) gemm_att(const float* attn_arg)
{
    extern __shared__ char smem[];
    uint32_t sb = smem_u32(smem);
    int tid = threadIdx.x, wid = tid >> 5, lane = tid & 31;
    const float* attn = attn_arg ? attn_arg : g_attn_fb;
    int hb = blockIdx.z, h = hb >> 1, b = hb & 1;
    int m0 = blockIdx.x * 128;
    const float* A = attn + (size_t)hb * SN * SN + (size_t)m0 * SN;
    int wm = wid & 3, wn = wid >> 2;

    float va[32];
    loadA_regs(va, A, SN, tid);
    cp_tile(sb + 32768, g_vt_hi[hb], SN, tid, 64);
    cp_tile(sb + 40960, g_vt_lo[hb], SN, tid, 64);
    CP_COMMIT();

    float acc[2][4][4] = {};
    int cur = 0, nxt = 1;
#pragma unroll 1
    for (int s = 0; s < 32; s++) {
        uint32_t bs = sb + cur * ASTAGE;
        storeA_split(bs, bs + 16384, va, tid);   // A chunk s -> ring slot cur
        if (s < 31) {
            int kc = (s + 1) * 64;
            uint32_t nb = sb + nxt * ASTAGE;
            cp_tile(nb + 32768, g_vt_hi[hb] + kc, SN, tid, 64);
            cp_tile(nb + 40960, g_vt_lo[hb] + kc, SN, tid, 64);
            CP_COMMIT();
            CP_WAIT1();
        } else {
            CP_WAIT0();
        }
        __syncthreads();   // single barrier: A-split + B stage visible
        if (s < 31) loadA_regs(va, A + (s + 1) * 64, SN, tid);
#pragma unroll
        for (int ks = 0; ks < 4; ks++) {
            uint32_t ah[2][4], al[2][4], bh[4][2], bl[4][2];
            int acol = ks * 32 + (lane >> 4) * 16;
#pragma unroll
            for (int mi = 0; mi < 2; mi++) {
                int arow = wm * 32 + mi * 16 + (lane & 15);
                uint32_t off = SWZ((uint32_t)(arow * 128 + acol));
                ldmx4(ah[mi], bs + off);
                ldmx4(al[mi], bs + 16384 + off);
            }
            int bcol = ks * 32 + ((lane >> 3) & 1) * 16;
#pragma unroll
            for (int nj = 0; nj < 2; nj++) {
                int brow = wn * 32 + nj * 16 + (lane & 7) + (lane >> 4) * 8;
                uint32_t off = SWZ((uint32_t)(brow * 128 + bcol));
                uint32_t t[4];
                ldmx4(t, bs + 32768 + off);
                bh[nj * 2][0] = t[0]; bh[nj * 2][1] = t[1];
                bh[nj * 2 + 1][0] = t[2]; bh[nj * 2 + 1][1] = t[3];
                ldmx4(t, bs + 40960 + off);
                bl[nj * 2][0] = t[0]; bl[nj * 2][1] = t[1];
                bl[nj * 2 + 1][0] = t[2]; bl[nj * 2 + 1][1] = t[3];
            }
#pragma unroll
            for (int mi = 0; mi < 2; mi++)
#pragma unroll
                for (int ni = 0; ni < 4; ni++) {
                    mma16816(acc[mi][ni], ah[mi], bh[ni]);
                    mma16816(acc[mi][ni], ah[mi], bl[ni]);
                    mma16816(acc[mi][ni], al[mi], bh[ni]);
                }
        }
        cur = nxt; nxt = (nxt == 2) ? 0 : nxt + 1;
    }

    size_t rbase = (size_t)(b * SN + m0) + wm * 32;
    int cbase = h * EN + wn * 32;
#pragma unroll
    for (int mi = 0; mi < 2; mi++)
#pragma unroll
        for (int ni = 0; ni < 4; ni++) {
            size_t r0 = rbase + mi * 16 + (lane >> 2);
            int c = cbase + ni * 8 + (lane & 3) * 2;
            store_split2(g_cat_hi, g_cat_lo, r0 * DN + c,       acc[mi][ni][0], acc[mi][ni][1]);
            store_split2(g_cat_hi, g_cat_lo, (r0 + 8) * DN + c, acc[mi][ni][2], acc[mi][ni][3]);
        }
}

// ---------------------------------------------------------------------------
// Output GEMM: 3-stage ring, single barrier per chunk. grid (32, 8)
// ---------------------------------------------------------------------------
__global__ void __launch_bounds__(256) gemm_out(float* __restrict__ out)
{
    extern __shared__ char smem[];
    uint32_t sb = smem_u32(smem);
    int tid = threadIdx.x, wid = tid >> 5, lane = tid & 31;
    int m0 = blockIdx.x * 128, n0 = blockIdx.y * 128;
    int wm = wid & 1, wn = wid >> 1;

    issue4(sb, g_cat_hi + (size_t)m0 * DN, g_cat_lo + (size_t)m0 * DN,
           g_w_hi[3] + (size_t)n0 * DN, g_w_lo[3] + (size_t)n0 * DN, tid);
    CP_COMMIT();

    float acc[4][4][4] = {};
    int cur = 0, nxt = 1;
#pragma unroll 1
    for (int s = 0; s < 16; s++) {
        if (s < 15) {
            int kc = (s + 1) * 64;
            issue4(sb + nxt * PSTAGE, g_cat_hi + (size_t)m0 * DN + kc, g_cat_lo + (size_t)m0 * DN + kc,
                   g_w_hi[3] + (size_t)n0 * DN + kc, g_w_lo[3] + (size_t)n0 * DN + kc, tid);
            CP_COMMIT();
            CP_WAIT1();
        } else {
            CP_WAIT0();
        }
        __syncthreads();
        mma_chunk_128(acc, sb + cur * PSTAGE, wm, wn, lane);
        cur = nxt; nxt = (nxt == 2) ? 0 : nxt + 1;
    }

    size_t rbase = (size_t)m0 + wm * 64;
    int cbase = n0 + wn * 32;
#pragma unroll
    for (int mi = 0; mi < 4; mi++)
#pragma unroll
        for (int ni = 0; ni < 4; ni++) {
            size_t r0 = rbase + mi * 16 + (lane >> 2);
            int c = cbase + ni * 8 + (lane & 3) * 2;
            *(float2*)(out + r0 * DN + c)       = make_float2(acc[mi][ni][0], acc[mi][ni][1]);
            *(float2*)(out + (r0 + 8) * DN + c) = make_float2(acc[mi][ni][2], acc[mi][ni][3]);
        }
}

// ---------------------------------------------------------------------------
extern "C" void kernel_launch(void* const* d_in, const int* in_sizes, int n_in,
                              void* d_out, int out_size)
{
    const float* acts[3] = {nullptr, nullptr, nullptr};
    const float* wts[4]  = {nullptr, nullptr, nullptr, nullptr};
    int na = 0, nw = 0;
    for (int i = 0; i < n_in; i++) {
        if (in_sizes[i] == BSN * DN && na < 3) acts[na++] = (const float*)d_in[i];
        else if (nw < 4)                       wts[nw++]  = (const float*)d_in[i];
    }
    if (na != 3 || nw != 4) {
        acts[0] = (const float*)d_in[0]; acts[1] = (const float*)d_in[1]; acts[2] = (const float*)d_in[2];
        wts[0]  = (const float*)d_in[3]; wts[1]  = (const float*)d_in[4];
        wts[2]  = (const float*)d_in[5]; wts[3]  = (const float*)d_in[6];
    }
    const float* q  = acts[0];
    const float* k  = acts[1];
    const float* v  = acts[2];
    const float* Wq = wts[0];
    const float* Wk = wts[1];
    const float* Wv = wts[2];
    const float* Wo = wts[3];
    float* out = (float*)d_out;

    const long long OUT_E  = (long long)BSN * DN;
    const long long ATTN_E = (long long)HBN * SN * SN;
    float* attn_ptr = ((long long)out_size >= OUT_E + ATTN_E) ? (out + OUT_E) : nullptr;

    cudaFuncSetAttribute(gemm_proj,   cudaFuncAttributeMaxDynamicSharedMemorySize, SMEM_PIPE);
    cudaFuncSetAttribute(gemm_scores, cudaFuncAttributeMaxDynamicSharedMemorySize, SMEM_SCORES);
    cudaFuncSetAttribute(gemm_att,    cudaFuncAttributeMaxDynamicSharedMemorySize, SMEM_ATT);
    cudaFuncSetAttribute(gemm_out,    cudaFuncAttributeMaxDynamicSharedMemorySize, SMEM_PIPE);

    xsplit_kernel<<<dim3(2048, 3), 256>>>(q, k, v);
    wsplit_qkv<<<dim3(32, 2, 48), dim3(32, 8)>>>(Wq, Wk, Wv);
    wsplit_o<<<dim3(32, 32), dim3(32, 8)>>>(Wo);
    gemm_proj<<<dim3(32, 8, 3), 256, SMEM_PIPE>>>(0);
    vtrans_kernel<<<dim3(64, 2, 32), dim3(32, 8)>>>();
    gemm_scores<<<dim3(16, 16, 32), 256, SMEM_SCORES>>>(attn_ptr);
    softmax_kernel<<<dim3(HBN * SN), 256>>>(attn_ptr);
    gemm_att<<<dim3(16, 1, 32), 256, SMEM_ATT>>>(attn_ptr);
    gemm_out<<<dim3(32, 8), 256, SMEM_PIPE>>>(out);
}

// round 11
// speedup vs baseline: 1.9811x; 1.0040x over previous
#include <cuda_runtime.h>
#include <cuda_bf16.h>
#include <cstdint>

#define HN 16
#define BN_ 2
#define SN 2048
#define DN 1024
#define EN 64
#define BSN 4096
#define HBN 32

// ---------------- device scratch (allocation-free rule) ----------------
__device__ __align__(256) __nv_bfloat16 g_w_hi[4][DN * DN];   // [z][n][k]
__device__ __align__(256) __nv_bfloat16 g_w_lo[4][DN * DN];
__device__ __align__(256) __nv_bfloat16 g_x_hi[3][BSN * DN];  // q/k/v split [b*S+s][d]
__device__ __align__(256) __nv_bfloat16 g_x_lo[3][BSN * DN];
__device__ __align__(256) __nv_bfloat16 g_p_hi[3][BSN * DN];  // qh/kh/vh split
__device__ __align__(256) __nv_bfloat16 g_p_lo[3][BSN * DN];
__device__ __align__(256) __nv_bfloat16 g_vt_hi[HBN][EN * SN]; // V^T per head
__device__ __align__(256) __nv_bfloat16 g_vt_lo[HBN][EN * SN];
__device__ __align__(256) __nv_bfloat16 g_cat_hi[BSN * DN];
__device__ __align__(256) __nv_bfloat16 g_cat_lo[BSN * DN];
__device__ __align__(256) float g_attn_fb[(size_t)HBN * SN * SN];

// ---------------- helpers ----------------
__device__ __forceinline__ uint32_t smem_u32(const void* p) {
    uint32_t a;
    asm("{ .reg .u64 t; cvta.to.shared.u64 t, %1; cvt.u32.u64 %0, t; }" : "=r"(a) : "l"(p));
    return a;
}
#define SWZ(x) ((x) ^ (((x) >> 3) & 0x70))

__device__ __forceinline__ void sts128(uint32_t addr, uint4 v) {
    asm volatile("st.shared.v4.b32 [%0], {%1,%2,%3,%4};"
                 :: "r"(addr), "r"(v.x), "r"(v.y), "r"(v.z), "r"(v.w) : "memory");
}
__device__ __forceinline__ uint32_t bpair(float a, float b) {
    uint32_t r;
    asm("cvt.rn.bf16x2.f32 %0, %1, %2;" : "=r"(r) : "f"(b), "f"(a));
    return r;
}
__device__ __forceinline__ void ldmx4(uint32_t* r, uint32_t addr) {
    asm volatile("ldmatrix.sync.aligned.m8n8.x4.shared.b16 {%0,%1,%2,%3}, [%4];"
                 : "=r"(r[0]), "=r"(r[1]), "=r"(r[2]), "=r"(r[3]) : "r"(addr));
}
__device__ __forceinline__ void mma16816(float* d, const uint32_t* a, const uint32_t* b) {
    asm volatile("mma.sync.aligned.m16n8k16.row.col.f32.bf16.bf16.f32 "
        "{%0,%1,%2,%3}, {%4,%5,%6,%7}, {%8,%9}, {%0,%1,%2,%3};"
        : "+f"(d[0]), "+f"(d[1]), "+f"(d[2]), "+f"(d[3])
        : "r"(a[0]), "r"(a[1]), "r"(a[2]), "r"(a[3]), "r"(b[0]), "r"(b[1]));
}
__device__ __forceinline__ void store_split2(__nv_bfloat16* Chi, __nv_bfloat16* Clo,
                                             size_t off, float v0, float v1) {
    float h0 = __bfloat162float(__float2bfloat16(v0));
    float h1 = __bfloat162float(__float2bfloat16(v1));
    *(uint32_t*)(Chi + off) = bpair(h0, h1);
    *(uint32_t*)(Clo + off) = bpair(v0 - h0, v1 - h1);
}

// cp.async 16B
__device__ __forceinline__ void cpa16(uint32_t dst, const void* src) {
    asm volatile("cp.async.cg.shared.global [%0], [%1], 16;" :: "r"(dst), "l"(src) : "memory");
}
#define CP_COMMIT() asm volatile("cp.async.commit_group;" ::: "memory")
#define CP_WAIT1()  asm volatile("cp.async.wait_group 1;" ::: "memory")
#define CP_WAIT0()  asm volatile("cp.async.wait_group 0;" ::: "memory")

__device__ __forceinline__ void cp_tile(uint32_t dst, const __nv_bfloat16* __restrict__ src,
                                        int ld, int tid, int rows) {
    int nchunk = rows * 8;
    for (int c = tid; c < nchunk; c += 256) {
        int r = c >> 3, g = c & 7;
        cpa16(dst + SWZ((uint32_t)(r * 128 + g * 16)), src + (size_t)r * ld + g * 8);
    }
}
__device__ __forceinline__ void load_b16(uint32_t dst, const __nv_bfloat16* __restrict__ src,
                                         int ld, int tid, int rows) {
    int nchunk = rows * 8;
    for (int c = tid; c < nchunk; c += 256) {
        int r = c >> 3, g = c & 7;
        uint4 v = *(const uint4*)(src + (size_t)r * ld + g * 8);
        sts128(dst + SWZ((uint32_t)(r * 128 + g * 16)), v);
    }
}

// A-prefetch for att: 128x64 fp32 chunk -> 32 regs/thread
__device__ __forceinline__ void loadA_regs(float* va, const float* __restrict__ src,
                                           int ld, int tid) {
#pragma unroll
    for (int it = 0; it < 4; it++) {
        int c = tid + it * 256;
        int r = c >> 3, g = c & 7;
        const float* p = src + (size_t)r * ld + g * 8;
        float4 f0 = *(const float4*)p;
        float4 f1 = *(const float4*)(p + 4);
        va[it * 8 + 0] = f0.x; va[it * 8 + 1] = f0.y; va[it * 8 + 2] = f0.z; va[it * 8 + 3] = f0.w;
        va[it * 8 + 4] = f1.x; va[it * 8 + 5] = f1.y; va[it * 8 + 6] = f1.z; va[it * 8 + 7] = f1.w;
    }
}
__device__ __forceinline__ void storeA_split(uint32_t dhi, uint32_t dlo, const float* va, int tid) {
#pragma unroll
    for (int it = 0; it < 4; it++) {
        int c = tid + it * 256;
        int r = c >> 3, g = c & 7;
        uint4 H, L;
        uint32_t* Hp = (uint32_t*)&H;
        uint32_t* Lp = (uint32_t*)&L;
#pragma unroll
        for (int pp = 0; pp < 4; pp++) {
            float v0 = va[it * 8 + pp * 2], v1 = va[it * 8 + pp * 2 + 1];
            float h0 = __bfloat162float(__float2bfloat16(v0));
            float h1 = __bfloat162float(__float2bfloat16(v1));
            Hp[pp] = bpair(h0, h1);
            Lp[pp] = bpair(v0 - h0, v1 - h1);
        }
        uint32_t ad = SWZ((uint32_t)(r * 128 + g * 16));
        sts128(dhi + ad, H);
        sts128(dlo + ad, L);
    }
}

// smem stage layouts: 3-stage rings
#define PSTAGE 65536          // proj/out: AH 16K | AL 16K | BH 16K | BL 16K
#define SMEM_PIPE (3 * PSTAGE)   // 192 KB
#define ASTAGE 49152          // att: AH 16K | AL 16K | BH 8K | BL 8K
#define SMEM_ATT (3 * ASTAGE)    // 144 KB
#define SMEM_SCORES 65536

// ===========================================================================
// mma core on one stage: 128x128 tile, 8 warps (2x4), warp 64x32.
// Term-major issue order: all 16 independent accumulators per split-term,
// so no back-to-back RAW chains on the tensor pipe.
// ===========================================================================
__device__ __forceinline__ void mma_chunk_128(float acc[4][4][4], uint32_t bs,
                                              int wm, int wn, int lane) {
#pragma unroll
    for (int ks = 0; ks < 4; ks++) {
        uint32_t ah[4][4], al[4][4], bh[4][2], bl[4][2];
        int acol = ks * 32 + (lane >> 4) * 16;
#pragma unroll
        for (int mi = 0; mi < 4; mi++) {
            int arow = wm * 64 + mi * 16 + (lane & 15);
            uint32_t off = SWZ((uint32_t)(arow * 128 + acol));
            ldmx4(ah[mi], bs + off);
            ldmx4(al[mi], bs + 16384 + off);
        }
        int bcol = ks * 32 + ((lane >> 3) & 1) * 16;
#pragma unroll
        for (int nj = 0; nj < 2; nj++) {
            int brow = wn * 32 + nj * 16 + (lane & 7) + (lane >> 4) * 8;
            uint32_t off = SWZ((uint32_t)(brow * 128 + bcol));
            uint32_t t[4];
            ldmx4(t, bs + 32768 + off);
            bh[nj * 2][0] = t[0]; bh[nj * 2][1] = t[1];
            bh[nj * 2 + 1][0] = t[2]; bh[nj * 2 + 1][1] = t[3];
            ldmx4(t, bs + 49152 + off);
            bl[nj * 2][0] = t[0]; bl[nj * 2][1] = t[1];
            bl[nj * 2 + 1][0] = t[2]; bl[nj * 2 + 1][1] = t[3];
        }
        // term hh
#pragma unroll
        for (int mi = 0; mi < 4; mi++)
#pragma unroll
            for (int ni = 0; ni < 4; ni++)
                mma16816(acc[mi][ni], ah[mi], bh[ni]);
        // term hl
#pragma unroll
        for (int mi = 0; mi < 4; mi++)
#pragma unroll
            for (int ni = 0; ni < 4; ni++)
                mma16816(acc[mi][ni], ah[mi], bl[ni]);
        // term lh
#pragma unroll
        for (int mi = 0; mi < 4; mi++)
#pragma unroll
            for (int ni = 0; ni < 4; ni++)
                mma16816(acc[mi][ni], al[mi], bh[ni]);
    }
}

// ---------------------------------------------------------------------------
// xsplit: q/k/v fp32 -> bf16 hi/lo. grid (2048, 3)
// ---------------------------------------------------------------------------
__global__ void __launch_bounds__(256) xsplit_kernel(
    const float* __restrict__ q, const float* __restrict__ k, const float* __restrict__ v)
{
    int z = blockIdx.y;
    const float* X = (z == 0) ? q : ((z == 1) ? k : v);
    size_t idx = ((size_t)blockIdx.x * 256 + threadIdx.x) * 8;
    float4 f0 = *(const float4*)(X + idx);
    float4 f1 = *(const float4*)(X + idx + 4);
    float val[8] = {f0.x, f0.y, f0.z, f0.w, f1.x, f1.y, f1.z, f1.w};
    uint4 H, L;
    uint32_t* Hp = (uint32_t*)&H;
    uint32_t* Lp = (uint32_t*)&L;
#pragma unroll
    for (int pp = 0; pp < 4; pp++) {
        float h0 = __bfloat162float(__float2bfloat16(val[pp * 2]));
        float h1 = __bfloat162float(__float2bfloat16(val[pp * 2 + 1]));
        Hp[pp] = bpair(h0, h1);
        Lp[pp] = bpair(val[pp * 2] - h0, val[pp * 2 + 1] - h1);
    }
    *(uint4*)(g_x_hi[z] + idx) = H;
    *(uint4*)(g_x_lo[z] + idx) = L;
}

// ---------------------------------------------------------------------------
// Weight transpose+split (unchanged)
// ---------------------------------------------------------------------------
__global__ void __launch_bounds__(256) wsplit_qkv(
    const float* __restrict__ wq, const float* __restrict__ wk, const float* __restrict__ wv)
{
    __shared__ float tile[32][33];
    int z = blockIdx.z >> 4, h = blockIdx.z & 15;
    const float* W = (z == 0) ? wq : ((z == 1) ? wk : wv);
    int d0 = blockIdx.x * 32, e0 = blockIdx.y * 32;
    int tx = threadIdx.x, ty = threadIdx.y;
#pragma unroll
    for (int i = 0; i < 4; i++) {
        int d = d0 + ty + i * 8;
        tile[ty + i * 8][tx] = W[(size_t)h * DN * EN + (size_t)d * EN + e0 + tx];
    }
    __syncthreads();
#pragma unroll
    for (int i = 0; i < 4; i++) {
        int e = e0 + ty + i * 8;
        int n = h * EN + e, k = d0 + tx;
        float v = tile[tx][ty + i * 8];
        float hf = __bfloat162float(__float2bfloat16(v));
        g_w_hi[z][(size_t)n * DN + k] = __float2bfloat16(hf);
        g_w_lo[z][(size_t)n * DN + k] = __float2bfloat16(v - hf);
    }
}

__global__ void __launch_bounds__(256) wsplit_o(const float* __restrict__ wo)
{
    __shared__ float tile[32][33];
    int k0 = blockIdx.x * 32, n0 = blockIdx.y * 32;
    int tx = threadIdx.x, ty = threadIdx.y;
#pragma unroll
    for (int i = 0; i < 4; i++)
        tile[ty + i * 8][tx] = wo[(size_t)(k0 + ty + i * 8) * DN + n0 + tx];
    __syncthreads();
#pragma unroll
    for (int i = 0; i < 4; i++) {
        int n = n0 + ty + i * 8, k = k0 + tx;
        float v = tile[tx][ty + i * 8];
        float hf = __bfloat162float(__float2bfloat16(v));
        g_w_hi[3][(size_t)n * DN + k] = __float2bfloat16(hf);
        g_w_lo[3][(size_t)n * DN + k] = __float2bfloat16(v - hf);
    }
}

__global__ void __launch_bounds__(256) vtrans_kernel()
{
    __shared__ __nv_bfloat16 th[32][33];
    __shared__ __nv_bfloat16 tl[32][33];
    int hb = blockIdx.z, h = hb >> 1, b = hb & 1;
    int s0 = blockIdx.x * 32, e0 = blockIdx.y * 32;
    int tx = threadIdx.x, ty = threadIdx.y;
#pragma unroll
    for (int i = 0; i < 4; i++) {
        size_t src = (size_t)(b * SN + s0 + ty + i * 8) * DN + h * EN + e0 + tx;
        th[ty + i * 8][tx] = g_p_hi[2][src];
        tl[ty + i * 8][tx] = g_p_lo[2][src];
    }
    __syncthreads();
#pragma unroll
    for (int i = 0; i < 4; i++) {
        int e = e0 + ty + i * 8;
        size_t dst = (size_t)e * SN + s0 + tx;
        g_vt_hi[hb][dst] = th[tx][ty + i * 8];
        g_vt_lo[hb][dst] = tl[tx][ty + i * 8];
    }
}

// ---------------------------------------------------------------------------
// Projection GEMM: 3-stage cp.async ring, one barrier per chunk. grid (32,8,3)
// ---------------------------------------------------------------------------
__device__ __forceinline__ void issue4(uint32_t base,
    const __nv_bfloat16* ah, const __nv_bfloat16* al,
    const __nv_bfloat16* bh, const __nv_bfloat16* bl, int tid) {
    cp_tile(base,         ah, DN, tid, 128);
    cp_tile(base + 16384, al, DN, tid, 128);
    cp_tile(base + 32768, bh, DN, tid, 128);
    cp_tile(base + 49152, bl, DN, tid, 128);
}

__global__ void __launch_bounds__(256) gemm_proj(int dummy)
{
    extern __shared__ char smem[];
    uint32_t sb = smem_u32(smem);
    int tid = threadIdx.x, wid = tid >> 5, lane = tid & 31;
    int z = blockIdx.z;
    const __nv_bfloat16* Axh = g_x_hi[z];
    const __nv_bfloat16* Axl = g_x_lo[z];
    const __nv_bfloat16* Bhi = g_w_hi[z];
    const __nv_bfloat16* Blo = g_w_lo[z];
    __nv_bfloat16* Chi = g_p_hi[z];
    __nv_bfloat16* Clo = g_p_lo[z];
    int m0 = blockIdx.x * 128, n0 = blockIdx.y * 128;
    int wm = wid & 1, wn = wid >> 1;

    issue4(sb, Axh + (size_t)m0 * DN, Axl + (size_t)m0 * DN,
           Bhi + (size_t)n0 * DN, Blo + (size_t)n0 * DN, tid);
    CP_COMMIT();

    float acc[4][4][4] = {};
    int cur = 0, nxt = 1;
#pragma unroll 1
    for (int s = 0; s < 16; s++) {
        if (s < 15) {
            int kc = (s + 1) * 64;
            issue4(sb + nxt * PSTAGE, Axh + (size_t)m0 * DN + kc, Axl + (size_t)m0 * DN + kc,
                   Bhi + (size_t)n0 * DN + kc, Blo + (size_t)n0 * DN + kc, tid);
            CP_COMMIT();
            CP_WAIT1();
        } else {
            CP_WAIT0();
        }
        __syncthreads();
        mma_chunk_128(acc, sb + cur * PSTAGE, wm, wn, lane);
        cur = nxt; nxt = (nxt == 2) ? 0 : nxt + 1;
    }

    size_t rbase = (size_t)m0 + wm * 64;
    int cbase = n0 + wn * 32;
#pragma unroll
    for (int mi = 0; mi < 4; mi++)
#pragma unroll
        for (int ni = 0; ni < 4; ni++) {
            size_t r0 = rbase + mi * 16 + (lane >> 2);
            int c = cbase + ni * 8 + (lane & 3) * 2;
            store_split2(Chi, Clo, r0 * DN + c,       acc[mi][ni][0], acc[mi][ni][1]);
            store_split2(Chi, Clo, (r0 + 8) * DN + c, acc[mi][ni][2], acc[mi][ni][3]);
        }
}

// ---------------------------------------------------------------------------
// Scores GEMM (K=64, single chunk). grid (16,16,32)
// ---------------------------------------------------------------------------
__global__ void __launch_bounds__(256) gemm_scores(float* attn_arg)
{
    extern __shared__ char smem[];
    uint32_t sb = smem_u32(smem);
    int tid = threadIdx.x, wid = tid >> 5, lane = tid & 31;
    float* attn = attn_arg ? attn_arg : g_attn_fb;
    int hb = blockIdx.z, h = hb >> 1, b = hb & 1;
    int m0 = blockIdx.x * 128, n0 = blockIdx.y * 128;
    const __nv_bfloat16* Ah = g_p_hi[0] + (size_t)(b * SN + m0) * DN + h * EN;
    const __nv_bfloat16* Al = g_p_lo[0] + (size_t)(b * SN + m0) * DN + h * EN;
    const __nv_bfloat16* Bh = g_p_hi[1] + (size_t)(b * SN + n0) * DN + h * EN;
    const __nv_bfloat16* Bl = g_p_lo[1] + (size_t)(b * SN + n0) * DN + h * EN;
    float* C = attn + (size_t)hb * SN * SN;
    int wm = wid & 1, wn = wid >> 1;

    load_b16(sb,         Ah, DN, tid, 128);
    load_b16(sb + 16384, Al, DN, tid, 128);
    load_b16(sb + 32768, Bh, DN, tid, 128);
    load_b16(sb + 49152, Bl, DN, tid, 128);
    __syncthreads();

    float acc[4][4][4] = {};
    mma_chunk_128(acc, sb, wm, wn, lane);

    const float sc = 1.0f / 64.0f;
    size_t rbase = (size_t)m0 + wm * 64;
    int cbase = n0 + wn * 32;
#pragma unroll
    for (int mi = 0; mi < 4; mi++)
#pragma unroll
        for (int ni = 0; ni < 4; ni++) {
            size_t r0 = rbase + mi * 16 + (lane >> 2);
            int c = cbase + ni * 8 + (lane & 3) * 2;
            *(float2*)(C + r0 * SN + c)       = make_float2(acc[mi][ni][0] * sc, acc[mi][ni][1] * sc);
            *(float2*)(C + (r0 + 8) * SN + c) = make_float2(acc[mi][ni][2] * sc, acc[mi][ni][3] * sc);
        }
}

// ---------------------------------------------------------------------------
// Row softmax (unchanged)
// ---------------------------------------------------------------------------
__global__ void __launch_bounds__(256) softmax_kernel(float* attn_arg)
{
    float* attn = attn_arg ? attn_arg : g_attn_fb;
    size_t row = blockIdx.x;
    float* p = attn + row * (size_t)SN;
    int tid = threadIdx.x;

    float4 v0 = *(float4*)(p + tid * 8);
    float4 v1 = *(float4*)(p + tid * 8 + 4);

    float m = fmaxf(fmaxf(fmaxf(v0.x, v0.y), fmaxf(v0.z, v0.w)),
                    fmaxf(fmaxf(v1.x, v1.y), fmaxf(v1.z, v1.w)));
    __shared__ float sm[8];
#pragma unroll
    for (int o = 16; o > 0; o >>= 1) m = fmaxf(m, __shfl_xor_sync(0xffffffffu, m, o));
    if ((tid & 31) == 0) sm[tid >> 5] = m;
    __syncthreads();
    if (tid < 32) {
        float t = (tid < 8) ? sm[tid] : -3.0e38f;
#pragma unroll
        for (int o = 4; o > 0; o >>= 1) t = fmaxf(t, __shfl_xor_sync(0xffffffffu, t, o));
        if (tid == 0) sm[0] = t;
    }
    __syncthreads();
    m = sm[0];
    __syncthreads();

    float e0 = __expf(v0.x - m), e1 = __expf(v0.y - m), e2 = __expf(v0.z - m), e3 = __expf(v0.w - m);
    float e4 = __expf(v1.x - m), e5 = __expf(v1.y - m), e6 = __expf(v1.z - m), e7 = __expf(v1.w - m);
    float s = ((e0 + e1) + (e2 + e3)) + ((e4 + e5) + (e6 + e7));
#pragma unroll
    for (int o = 16; o > 0; o >>= 1) s += __shfl_xor_sync(0xffffffffu, s, o);
    if ((tid & 31) == 0) sm[tid >> 5] = s;
    __syncthreads();
    if (tid < 32) {
        float t = (tid < 8) ? sm[tid] : 0.0f;
#pragma unroll
        for (int o = 4; o > 0; o >>= 1) t += __shfl_xor_sync(0xffffffffu, t, o);
        if (tid == 0) sm[0] = t;
    }
    __syncthreads();
    float inv = 1.0f / sm[0];

    *(float4*)(p + tid * 8)     = make_float4(e0 * inv, e1 * inv, e2 * inv, e3 * inv);
    *(float4*)(p + tid * 8 + 4) = make_float4(e4 * inv, e5 * inv, e6 * inv, e7 * inv);
}

// ---------------------------------------------------------------------------
// att GEMM: 3-stage ring, term-major mma order. grid (16,1,32)
// ---------------------------------------------------------------------------
__global__ void __launch_bounds__(256) gemm_att(const float* attn_arg)
{
    extern __shared__ char smem[];
    uint32_t sb = smem_u32(smem);
    int tid = threadIdx.x, wid = tid >> 5, lane = tid & 31;
    const float* attn = attn_arg ? attn_arg : g_attn_fb;
    int hb = blockIdx.z, h = hb >> 1, b = hb & 1;
    int m0 = blockIdx.x * 128;
    const float* A = attn + (size_t)hb * SN * SN + (size_t)m0 * SN;
    int wm = wid & 3, wn = wid >> 2;

    float va[32];
    loadA_regs(va, A, SN, tid);
    cp_tile(sb + 32768, g_vt_hi[hb], SN, tid, 64);
    cp_tile(sb + 40960, g_vt_lo[hb], SN, tid, 64);
    CP_COMMIT();

    float acc[2][4][4] = {};
    int cur = 0, nxt = 1;
#pragma unroll 1
    for (int s = 0; s < 32; s++) {
        uint32_t bs = sb + cur * ASTAGE;
        storeA_split(bs, bs + 16384, va, tid);
        if (s < 31) {
            int kc = (s + 1) * 64;
            uint32_t nb = sb + nxt * ASTAGE;
            cp_tile(nb + 32768, g_vt_hi[hb] + kc, SN, tid, 64);
            cp_tile(nb + 40960, g_vt_lo[hb] + kc, SN, tid, 64);
            CP_COMMIT();
            CP_WAIT1();
        } else {
            CP_WAIT0();
        }
        __syncthreads();
        if (s < 31) loadA_regs(va, A + (s + 1) * 64, SN, tid);
#pragma unroll
        for (int ks = 0; ks < 4; ks++) {
            uint32_t ah[2][4], al[2][4], bh[4][2], bl[4][2];
            int acol = ks * 32 + (lane >> 4) * 16;
#pragma unroll
            for (int mi = 0; mi < 2; mi++) {
                int arow = wm * 32 + mi * 16 + (lane & 15);
                uint32_t off = SWZ((uint32_t)(arow * 128 + acol));
                ldmx4(ah[mi], bs + off);
                ldmx4(al[mi], bs + 16384 + off);
            }
            int bcol = ks * 32 + ((lane >> 3) & 1) * 16;
#pragma unroll
            for (int nj = 0; nj < 2; nj++) {
                int brow = wn * 32 + nj * 16 + (lane & 7) + (lane >> 4) * 8;
                uint32_t off = SWZ((uint32_t)(brow * 128 + bcol));
                uint32_t t[4];
                ldmx4(t, bs + 32768 + off);
                bh[nj * 2][0] = t[0]; bh[nj * 2][1] = t[1];
                bh[nj * 2 + 1][0] = t[2]; bh[nj * 2 + 1][1] = t[3];
                ldmx4(t, bs + 40960 + off);
                bl[nj * 2][0] = t[0]; bl[nj * 2][1] = t[1];
                bl[nj * 2 + 1][0] = t[2]; bl[nj * 2 + 1][1] = t[3];
            }
            // term-major: 8 independent accs between RAW reuses
#pragma unroll
            for (int mi = 0; mi < 2; mi++)
#pragma unroll
                for (int ni = 0; ni < 4; ni++)
                    mma16816(acc[mi][ni], ah[mi], bh[ni]);
#pragma unroll
            for (int mi = 0; mi < 2; mi++)
#pragma unroll
                for (int ni = 0; ni < 4; ni++)
                    mma16816(acc[mi][ni], ah[mi], bl[ni]);
#pragma unroll
            for (int mi = 0; mi < 2; mi++)
#pragma unroll
                for (int ni = 0; ni < 4; ni++)
                    mma16816(acc[mi][ni], al[mi], bh[ni]);
        }
        cur = nxt; nxt = (nxt == 2) ? 0 : nxt + 1;
    }

    size_t rbase = (size_t)(b * SN + m0) + wm * 32;
    int cbase = h * EN + wn * 32;
#pragma unroll
    for (int mi = 0; mi < 2; mi++)
#pragma unroll
        for (int ni = 0; ni < 4; ni++) {
            size_t r0 = rbase + mi * 16 + (lane >> 2);
            int c = cbase + ni * 8 + (lane & 3) * 2;
            store_split2(g_cat_hi, g_cat_lo, r0 * DN + c,       acc[mi][ni][0], acc[mi][ni][1]);
            store_split2(g_cat_hi, g_cat_lo, (r0 + 8) * DN + c, acc[mi][ni][2], acc[mi][ni][3]);
        }
}

// ---------------------------------------------------------------------------
// Output GEMM: 3-stage ring. grid (32, 8)
// ---------------------------------------------------------------------------
__global__ void __launch_bounds__(256) gemm_out(float* __restrict__ out)
{
    extern __shared__ char smem[];
    uint32_t sb = smem_u32(smem);
    int tid = threadIdx.x, wid = tid >> 5, lane = tid & 31;
    int m0 = blockIdx.x * 128, n0 = blockIdx.y * 128;
    int wm = wid & 1, wn = wid >> 1;

    issue4(sb, g_cat_hi + (size_t)m0 * DN, g_cat_lo + (size_t)m0 * DN,
           g_w_hi[3] + (size_t)n0 * DN, g_w_lo[3] + (size_t)n0 * DN, tid);
    CP_COMMIT();

    float acc[4][4][4] = {};
    int cur = 0, nxt = 1;
#pragma unroll 1
    for (int s = 0; s < 16; s++) {
        if (s < 15) {
            int kc = (s + 1) * 64;
            issue4(sb + nxt * PSTAGE, g_cat_hi + (size_t)m0 * DN + kc, g_cat_lo + (size_t)m0 * DN + kc,
                   g_w_hi[3] + (size_t)n0 * DN + kc, g_w_lo[3] + (size_t)n0 * DN + kc, tid);
            CP_COMMIT();
            CP_WAIT1();
        } else {
            CP_WAIT0();
        }
        __syncthreads();
        mma_chunk_128(acc, sb + cur * PSTAGE, wm, wn, lane);
        cur = nxt; nxt = (nxt == 2) ? 0 : nxt + 1;
    }

    size_t rbase = (size_t)m0 + wm * 64;
    int cbase = n0 + wn * 32;
#pragma unroll
    for (int mi = 0; mi < 4; mi++)
#pragma unroll
        for (int ni = 0; ni < 4; ni++) {
            size_t r0 = rbase + mi * 16 + (lane >> 2);
            int c = cbase + ni * 8 + (lane & 3) * 2;
            *(float2*)(out + r0 * DN + c)       = make_float2(acc[mi][ni][0], acc[mi][ni][1]);
            *(float2*)(out + (r0 + 8) * DN + c) = make_float2(acc[mi][ni][2], acc[mi][ni][3]);
        }
}

// ---------------------------------------------------------------------------
extern "C" void kernel_launch(void* const* d_in, const int* in_sizes, int n_in,
                              void* d_out, int out_size)
{
    const float* acts[3] = {nullptr, nullptr, nullptr};
    const float* wts[4]  = {nullptr, nullptr, nullptr, nullptr};
    int na = 0, nw = 0;
    for (int i = 0; i < n_in; i++) {
        if (in_sizes[i] == BSN * DN && na < 3) acts[na++] = (const float*)d_in[i];
        else if (nw < 4)                       wts[nw++]  = (const float*)d_in[i];
    }
    if (na != 3 || nw != 4) {
        acts[0] = (const float*)d_in[0]; acts[1] = (const float*)d_in[1]; acts[2] = (const float*)d_in[2];
        wts[0]  = (const float*)d_in[3]; wts[1]  = (const float*)d_in[4];
        wts[2]  = (const float*)d_in[5]; wts[3]  = (const float*)d_in[6];
    }
    const float* q  = acts[0];
    const float* k  = acts[1];
    const float* v  = acts[2];
    const float* Wq = wts[0];
    const float* Wk = wts[1];
    const float* Wv = wts[2];
    const float* Wo = wts[3];
    float* out = (float*)d_out;

    const long long OUT_E  = (long long)BSN * DN;
    const long long ATTN_E = (long long)HBN * SN * SN;
    float* attn_ptr = ((long long)out_size >= OUT_E + ATTN_E) ? (out + OUT_E) : nullptr;

    cudaFuncSetAttribute(gemm_proj,   cudaFuncAttributeMaxDynamicSharedMemorySize, SMEM_PIPE);
    cudaFuncSetAttribute(gemm_scores, cudaFuncAttributeMaxDynamicSharedMemorySize, SMEM_SCORES);
    cudaFuncSetAttribute(gemm_att,    cudaFuncAttributeMaxDynamicSharedMemorySize, SMEM_ATT);
    cudaFuncSetAttribute(gemm_out,    cudaFuncAttributeMaxDynamicSharedMemorySize, SMEM_PIPE);

    xsplit_kernel<<<dim3(2048, 3), 256>>>(q, k, v);
    wsplit_qkv<<<dim3(32, 2, 48), dim3(32, 8)>>>(Wq, Wk, Wv);
    wsplit_o<<<dim3(32, 32), dim3(32, 8)>>>(Wo);
    gemm_proj<<<dim3(32, 8, 3), 256, SMEM_PIPE>>>(0);
    vtrans_kernel<<<dim3(64, 2, 32), dim3(32, 8)>>>();
    gemm_scores<<<dim3(16, 16, 32), 256, SMEM_SCORES>>>(attn_ptr);
    softmax_kernel<<<dim3(HBN * SN), 256>>>(attn_ptr);
    gemm_att<<<dim3(16, 1, 32), 256, SMEM_ATT>>>(attn_ptr);
    gemm_out<<<dim3(32, 8), 256, SMEM_PIPE>>>(out);
}

// round 12
// speedup vs baseline: 2.0306x; 1.0250x over previous
#include <cuda_runtime.h>
#include <cuda_bf16.h>
#include <cstdint>

#define HN 16
#define BN_ 2
#define SN 2048
#define DN 1024
#define EN 64
#define BSN 4096
#define HBN 32

// ---------------- device scratch (allocation-free rule) ----------------
__device__ __align__(256) __nv_bfloat16 g_w_hi[4][DN * DN];   // [z][n][k]
__device__ __align__(256) __nv_bfloat16 g_w_lo[4][DN * DN];
__device__ __align__(256) __nv_bfloat16 g_x_hi[3][BSN * DN];  // q/k/v split [b*S+s][d]
__device__ __align__(256) __nv_bfloat16 g_x_lo[3][BSN * DN];
__device__ __align__(256) __nv_bfloat16 g_p_hi[3][BSN * DN];  // qh/kh/vh split
__device__ __align__(256) __nv_bfloat16 g_p_lo[3][BSN * DN];
__device__ __align__(256) __nv_bfloat16 g_vt_hi[HBN][EN * SN]; // V^T per head
__device__ __align__(256) __nv_bfloat16 g_vt_lo[HBN][EN * SN];
__device__ __align__(256) __nv_bfloat16 g_cat_hi[BSN * DN];
__device__ __align__(256) __nv_bfloat16 g_cat_lo[BSN * DN];
__device__ __align__(256) float g_attn_fb[(size_t)HBN * SN * SN];

// ---------------- helpers ----------------
__device__ __forceinline__ uint32_t smem_u32(const void* p) {
    uint32_t a;
    asm("{ .reg .u64 t; cvta.to.shared.u64 t, %1; cvt.u32.u64 %0, t; }" : "=r"(a) : "l"(p));
    return a;
}
#define SWZ(x) ((x) ^ (((x) >> 3) & 0x70))

__device__ __forceinline__ void sts128(uint32_t addr, uint4 v) {
    asm volatile("st.shared.v4.b32 [%0], {%1,%2,%3,%4};"
                 :: "r"(addr), "r"(v.x), "r"(v.y), "r"(v.z), "r"(v.w) : "memory");
}
__device__ __forceinline__ uint32_t bpair(float a, float b) {
    uint32_t r;
    asm("cvt.rn.bf16x2.f32 %0, %1, %2;" : "=r"(r) : "f"(b), "f"(a));
    return r;
}
__device__ __forceinline__ void ldmx4(uint32_t* r, uint32_t addr) {
    asm volatile("ldmatrix.sync.aligned.m8n8.x4.shared.b16 {%0,%1,%2,%3}, [%4];"
                 : "=r"(r[0]), "=r"(r[1]), "=r"(r[2]), "=r"(r[3]) : "r"(addr));
}
__device__ __forceinline__ void mma16816(float* d, const uint32_t* a, const uint32_t* b) {
    asm volatile("mma.sync.aligned.m16n8k16.row.col.f32.bf16.bf16.f32 "
        "{%0,%1,%2,%3}, {%4,%5,%6,%7}, {%8,%9}, {%0,%1,%2,%3};"
        : "+f"(d[0]), "+f"(d[1]), "+f"(d[2]), "+f"(d[3])
        : "r"(a[0]), "r"(a[1]), "r"(a[2]), "r"(a[3]), "r"(b[0]), "r"(b[1]));
}
__device__ __forceinline__ void store_split2(__nv_bfloat16* Chi, __nv_bfloat16* Clo,
                                             size_t off, float v0, float v1) {
    float h0 = __bfloat162float(__float2bfloat16(v0));
    float h1 = __bfloat162float(__float2bfloat16(v1));
    *(uint32_t*)(Chi + off) = bpair(h0, h1);
    *(uint32_t*)(Clo + off) = bpair(v0 - h0, v1 - h1);
}

// cp.async 16B
__device__ __forceinline__ void cpa16(uint32_t dst, const void* src) {
    asm volatile("cp.async.cg.shared.global [%0], [%1], 16;" :: "r"(dst), "l"(src) : "memory");
}
#define CP_COMMIT() asm volatile("cp.async.commit_group;" ::: "memory")
#define CP_WAIT1()  asm volatile("cp.async.wait_group 1;" ::: "memory")
#define CP_WAIT0()  asm volatile("cp.async.wait_group 0;" ::: "memory")

__device__ __forceinline__ void cp_tile(uint32_t dst, const __nv_bfloat16* __restrict__ src,
                                        int ld, int tid, int rows) {
    int nchunk = rows * 8;
    for (int c = tid; c < nchunk; c += 256) {
        int r = c >> 3, g = c & 7;
        cpa16(dst + SWZ((uint32_t)(r * 128 + g * 16)), src + (size_t)r * ld + g * 8);
    }
}
__device__ __forceinline__ void load_b16(uint32_t dst, const __nv_bfloat16* __restrict__ src,
                                         int ld, int tid, int rows) {
    int nchunk = rows * 8;
    for (int c = tid; c < nchunk; c += 256) {
        int r = c >> 3, g = c & 7;
        uint4 v = *(const uint4*)(src + (size_t)r * ld + g * 8);
        sts128(dst + SWZ((uint32_t)(r * 128 + g * 16)), v);
    }
}

// direct global fp32 -> split bf16 hi/lo swizzled smem (128 rows x 64 cols)
__device__ __forceinline__ void storeA_direct(uint32_t dhi, uint32_t dlo,
                                              const float* __restrict__ src, int ld, int tid) {
#pragma unroll
    for (int it = 0; it < 4; it++) {
        int c = tid + it * 256;
        int r = c >> 3, g = c & 7;
        const float* p = src + (size_t)r * ld + g * 8;
        float4 f0 = *(const float4*)p;
        float4 f1 = *(const float4*)(p + 4);
        float v[8] = {f0.x, f0.y, f0.z, f0.w, f1.x, f1.y, f1.z, f1.w};
        uint4 H, L;
        uint32_t* Hp = (uint32_t*)&H;
        uint32_t* Lp = (uint32_t*)&L;
#pragma unroll
        for (int pp = 0; pp < 4; pp++) {
            float h0 = __bfloat162float(__float2bfloat16(v[pp * 2]));
            float h1 = __bfloat162float(__float2bfloat16(v[pp * 2 + 1]));
            Hp[pp] = bpair(h0, h1);
            Lp[pp] = bpair(v[pp * 2] - h0, v[pp * 2 + 1] - h1);
        }
        uint32_t ad = SWZ((uint32_t)(r * 128 + g * 16));
        sts128(dhi + ad, H);
        sts128(dlo + ad, L);
    }
}

// smem layouts
// N64 stage: AH 16K (128 rows) | AL 16K | BH 8K (64 rows) | BL 8K = 48 KB
#define NSTAGE 49152
#define SMEM_N64X2 (2 * NSTAGE)   // 96 KB -> 2 CTAs/SM
#define SMEM_SCORES 65536

// ===========================================================================
// mma core, 128x64 tile, 8 warps (4x2), warp 32x32. acc[2][4][4].
// Stage layout: AH=bs, AL=bs+16384, BH=bs+32768, BL=bs+40960.
// ===========================================================================
__device__ __forceinline__ void mma_chunk_64(float acc[2][4][4], uint32_t bs,
                                             int wm, int wn, int lane) {
#pragma unroll
    for (int ks = 0; ks < 4; ks++) {
        uint32_t ah[2][4], al[2][4], bh[4][2], bl[4][2];
        int acol = ks * 32 + (lane >> 4) * 16;
#pragma unroll
        for (int mi = 0; mi < 2; mi++) {
            int arow = wm * 32 + mi * 16 + (lane & 15);
            uint32_t off = SWZ((uint32_t)(arow * 128 + acol));
            ldmx4(ah[mi], bs + off);
            ldmx4(al[mi], bs + 16384 + off);
        }
        int bcol = ks * 32 + ((lane >> 3) & 1) * 16;
#pragma unroll
        for (int nj = 0; nj < 2; nj++) {
            int brow = wn * 32 + nj * 16 + (lane & 7) + (lane >> 4) * 8;
            uint32_t off = SWZ((uint32_t)(brow * 128 + bcol));
            uint32_t t[4];
            ldmx4(t, bs + 32768 + off);
            bh[nj * 2][0] = t[0]; bh[nj * 2][1] = t[1];
            bh[nj * 2 + 1][0] = t[2]; bh[nj * 2 + 1][1] = t[3];
            ldmx4(t, bs + 40960 + off);
            bl[nj * 2][0] = t[0]; bl[nj * 2][1] = t[1];
            bl[nj * 2 + 1][0] = t[2]; bl[nj * 2 + 1][1] = t[3];
        }
#pragma unroll
        for (int mi = 0; mi < 2; mi++)
#pragma unroll
            for (int ni = 0; ni < 4; ni++) {
                mma16816(acc[mi][ni], ah[mi], bh[ni]);
                mma16816(acc[mi][ni], ah[mi], bl[ni]);
                mma16816(acc[mi][ni], al[mi], bh[ni]);
            }
    }
}

// mma core, 128x128 tile (scores), 8 warps (2x4), warp 64x32. acc[4][4][4].
__device__ __forceinline__ void mma_chunk_128(float acc[4][4][4], uint32_t bs,
                                              int wm, int wn, int lane) {
#pragma unroll
    for (int ks = 0; ks < 4; ks++) {
        uint32_t ah[4][4], al[4][4], bh[4][2], bl[4][2];
        int acol = ks * 32 + (lane >> 4) * 16;
#pragma unroll
        for (int mi = 0; mi < 4; mi++) {
            int arow = wm * 64 + mi * 16 + (lane & 15);
            uint32_t off = SWZ((uint32_t)(arow * 128 + acol));
            ldmx4(ah[mi], bs + off);
            ldmx4(al[mi], bs + 16384 + off);
        }
        int bcol = ks * 32 + ((lane >> 3) & 1) * 16;
#pragma unroll
        for (int nj = 0; nj < 2; nj++) {
            int brow = wn * 32 + nj * 16 + (lane & 7) + (lane >> 4) * 8;
            uint32_t off = SWZ((uint32_t)(brow * 128 + bcol));
            uint32_t t[4];
            ldmx4(t, bs + 32768 + off);
            bh[nj * 2][0] = t[0]; bh[nj * 2][1] = t[1];
            bh[nj * 2 + 1][0] = t[2]; bh[nj * 2 + 1][1] = t[3];
            ldmx4(t, bs + 49152 + off);
            bl[nj * 2][0] = t[0]; bl[nj * 2][1] = t[1];
            bl[nj * 2 + 1][0] = t[2]; bl[nj * 2 + 1][1] = t[3];
        }
#pragma unroll
        for (int mi = 0; mi < 4; mi++)
#pragma unroll
            for (int ni = 0; ni < 4; ni++) {
                mma16816(acc[mi][ni], ah[mi], bh[ni]);
                mma16816(acc[mi][ni], ah[mi], bl[ni]);
                mma16816(acc[mi][ni], al[mi], bh[ni]);
            }
    }
}

// ---------------------------------------------------------------------------
// xsplit: q/k/v fp32 -> bf16 hi/lo. grid (2048, 3)
// ---------------------------------------------------------------------------
__global__ void __launch_bounds__(256) xsplit_kernel(
    const float* __restrict__ q, const float* __restrict__ k, const float* __restrict__ v)
{
    int z = blockIdx.y;
    const float* X = (z == 0) ? q : ((z == 1) ? k : v);
    size_t idx = ((size_t)blockIdx.x * 256 + threadIdx.x) * 8;
    float4 f0 = *(const float4*)(X + idx);
    float4 f1 = *(const float4*)(X + idx + 4);
    float val[8] = {f0.x, f0.y, f0.z, f0.w, f1.x, f1.y, f1.z, f1.w};
    uint4 H, L;
    uint32_t* Hp = (uint32_t*)&H;
    uint32_t* Lp = (uint32_t*)&L;
#pragma unroll
    for (int pp = 0; pp < 4; pp++) {
        float h0 = __bfloat162float(__float2bfloat16(val[pp * 2]));
        float h1 = __bfloat162float(__float2bfloat16(val[pp * 2 + 1]));
        Hp[pp] = bpair(h0, h1);
        Lp[pp] = bpair(val[pp * 2] - h0, val[pp * 2 + 1] - h1);
    }
    *(uint4*)(g_x_hi[z] + idx) = H;
    *(uint4*)(g_x_lo[z] + idx) = L;
}

// ---------------------------------------------------------------------------
// Weight transpose+split (unchanged)
// ---------------------------------------------------------------------------
__global__ void __launch_bounds__(256) wsplit_qkv(
    const float* __restrict__ wq, const float* __restrict__ wk, const float* __restrict__ wv)
{
    __shared__ float tile[32][33];
    int z = blockIdx.z >> 4, h = blockIdx.z & 15;
    const float* W = (z == 0) ? wq : ((z == 1) ? wk : wv);
    int d0 = blockIdx.x * 32, e0 = blockIdx.y * 32;
    int tx = threadIdx.x, ty = threadIdx.y;
#pragma unroll
    for (int i = 0; i < 4; i++) {
        int d = d0 + ty + i * 8;
        tile[ty + i * 8][tx] = W[(size_t)h * DN * EN + (size_t)d * EN + e0 + tx];
    }
    __syncthreads();
#pragma unroll
    for (int i = 0; i < 4; i++) {
        int e = e0 + ty + i * 8;
        int n = h * EN + e, k = d0 + tx;
        float v = tile[tx][ty + i * 8];
        float hf = __bfloat162float(__float2bfloat16(v));
        g_w_hi[z][(size_t)n * DN + k] = __float2bfloat16(hf);
        g_w_lo[z][(size_t)n * DN + k] = __float2bfloat16(v - hf);
    }
}

__global__ void __launch_bounds__(256) wsplit_o(const float* __restrict__ wo)
{
    __shared__ float tile[32][33];
    int k0 = blockIdx.x * 32, n0 = blockIdx.y * 32;
    int tx = threadIdx.x, ty = threadIdx.y;
#pragma unroll
    for (int i = 0; i < 4; i++)
        tile[ty + i * 8][tx] = wo[(size_t)(k0 + ty + i * 8) * DN + n0 + tx];
    __syncthreads();
#pragma unroll
    for (int i = 0; i < 4; i++) {
        int n = n0 + ty + i * 8, k = k0 + tx;
        float v = tile[tx][ty + i * 8];
        float hf = __bfloat162float(__float2bfloat16(v));
        g_w_hi[3][(size_t)n * DN + k] = __float2bfloat16(hf);
        g_w_lo[3][(size_t)n * DN + k] = __float2bfloat16(v - hf);
    }
}

__global__ void __launch_bounds__(256) vtrans_kernel()
{
    __shared__ __nv_bfloat16 th[32][33];
    __shared__ __nv_bfloat16 tl[32][33];
    int hb = blockIdx.z, h = hb >> 1, b = hb & 1;
    int s0 = blockIdx.x * 32, e0 = blockIdx.y * 32;
    int tx = threadIdx.x, ty = threadIdx.y;
#pragma unroll
    for (int i = 0; i < 4; i++) {
        size_t src = (size_t)(b * SN + s0 + ty + i * 8) * DN + h * EN + e0 + tx;
        th[ty + i * 8][tx] = g_p_hi[2][src];
        tl[ty + i * 8][tx] = g_p_lo[2][src];
    }
    __syncthreads();
#pragma unroll
    for (int i = 0; i < 4; i++) {
        int e = e0 + ty + i * 8;
        size_t dst = (size_t)e * SN + s0 + tx;
        g_vt_hi[hb][dst] = th[tx][ty + i * 8];
        g_vt_lo[hb][dst] = tl[tx][ty + i * 8];
    }
}

// ---------------------------------------------------------------------------
// Projection GEMM: 128x64 tile, 2-stage cp.async, 2 CTAs/SM. grid (32,16,3)
// ---------------------------------------------------------------------------
__device__ __forceinline__ void issue4_n64(uint32_t base,
    const __nv_bfloat16* ah, const __nv_bfloat16* al,
    const __nv_bfloat16* bh, const __nv_bfloat16* bl, int tid) {
    cp_tile(base,         ah, DN, tid, 128);
    cp_tile(base + 16384, al, DN, tid, 128);
    cp_tile(base + 32768, bh, DN, tid, 64);
    cp_tile(base + 40960, bl, DN, tid, 64);
}

__global__ void __launch_bounds__(256, 2) gemm_proj(int dummy)
{
    extern __shared__ char smem[];
    uint32_t sb = smem_u32(smem);
    int tid = threadIdx.x, wid = tid >> 5, lane = tid & 31;
    int z = blockIdx.z;
    const __nv_bfloat16* Axh = g_x_hi[z];
    const __nv_bfloat16* Axl = g_x_lo[z];
    const __nv_bfloat16* Bhi = g_w_hi[z];
    const __nv_bfloat16* Blo = g_w_lo[z];
    __nv_bfloat16* Chi = g_p_hi[z];
    __nv_bfloat16* Clo = g_p_lo[z];
    int m0 = blockIdx.x * 128, n0 = blockIdx.y * 64;
    int wm = wid & 3, wn = wid >> 2;

    issue4_n64(sb, Axh + (size_t)m0 * DN, Axl + (size_t)m0 * DN,
               Bhi + (size_t)n0 * DN, Blo + (size_t)n0 * DN, tid);
    CP_COMMIT();

    float acc[2][4][4] = {};
#pragma unroll 1
    for (int s = 0; s < 16; s++) {
        if (s < 15) {
            int kc = (s + 1) * 64;
            uint32_t nb = sb + ((s + 1) & 1) * NSTAGE;
            issue4_n64(nb, Axh + (size_t)m0 * DN + kc, Axl + (size_t)m0 * DN + kc,
                       Bhi + (size_t)n0 * DN + kc, Blo + (size_t)n0 * DN + kc, tid);
            CP_COMMIT();
            CP_WAIT1();
        } else {
            CP_WAIT0();
        }
        __syncthreads();
        mma_chunk_64(acc, sb + (s & 1) * NSTAGE, wm, wn, lane);
        __syncthreads();
    }

    size_t rbase = (size_t)m0 + wm * 32;
    int cbase = n0 + wn * 32;
#pragma unroll
    for (int mi = 0; mi < 2; mi++)
#pragma unroll
        for (int ni = 0; ni < 4; ni++) {
            size_t r0 = rbase + mi * 16 + (lane >> 2);
            int c = cbase + ni * 8 + (lane & 3) * 2;
            store_split2(Chi, Clo, r0 * DN + c,       acc[mi][ni][0], acc[mi][ni][1]);
            store_split2(Chi, Clo, (r0 + 8) * DN + c, acc[mi][ni][2], acc[mi][ni][3]);
        }
}

// ---------------------------------------------------------------------------
// Scores GEMM (K=64, single chunk). grid (16,16,32)
// ---------------------------------------------------------------------------
__global__ void __launch_bounds__(256) gemm_scores(float* attn_arg)
{
    extern __shared__ char smem[];
    uint32_t sb = smem_u32(smem);
    int tid = threadIdx.x, wid = tid >> 5, lane = tid & 31;
    float* attn = attn_arg ? attn_arg : g_attn_fb;
    int hb = blockIdx.z, h = hb >> 1, b = hb & 1;
    int m0 = blockIdx.x * 128, n0 = blockIdx.y * 128;
    const __nv_bfloat16* Ah = g_p_hi[0] + (size_t)(b * SN + m0) * DN + h * EN;
    const __nv_bfloat16* Al = g_p_lo[0] + (size_t)(b * SN + m0) * DN + h * EN;
    const __nv_bfloat16* Bh = g_p_hi[1] + (size_t)(b * SN + n0) * DN + h * EN;
    const __nv_bfloat16* Bl = g_p_lo[1] + (size_t)(b * SN + n0) * DN + h * EN;
    float* C = attn + (size_t)hb * SN * SN;
    int wm = wid & 1, wn = wid >> 1;

    load_b16(sb,         Ah, DN, tid, 128);
    load_b16(sb + 16384, Al, DN, tid, 128);
    load_b16(sb + 32768, Bh, DN, tid, 128);
    load_b16(sb + 49152, Bl, DN, tid, 128);
    __syncthreads();

    float acc[4][4][4] = {};
    mma_chunk_128(acc, sb, wm, wn, lane);

    const float sc = 1.0f / 64.0f;
    size_t rbase = (size_t)m0 + wm * 64;
    int cbase = n0 + wn * 32;
#pragma unroll
    for (int mi = 0; mi < 4; mi++)
#pragma unroll
        for (int ni = 0; ni < 4; ni++) {
            size_t r0 = rbase + mi * 16 + (lane >> 2);
            int c = cbase + ni * 8 + (lane & 3) * 2;
            *(float2*)(C + r0 * SN + c)       = make_float2(acc[mi][ni][0] * sc, acc[mi][ni][1] * sc);
            *(float2*)(C + (r0 + 8) * SN + c) = make_float2(acc[mi][ni][2] * sc, acc[mi][ni][3] * sc);
        }
}

// ---------------------------------------------------------------------------
// Row softmax (unchanged)
// ---------------------------------------------------------------------------
__global__ void __launch_bounds__(256) softmax_kernel(float* attn_arg)
{
    float* attn = attn_arg ? attn_arg : g_attn_fb;
    size_t row = blockIdx.x;
    float* p = attn + row * (size_t)SN;
    int tid = threadIdx.x;

    float4 v0 = *(float4*)(p + tid * 8);
    float4 v1 = *(float4*)(p + tid * 8 + 4);

    float m = fmaxf(fmaxf(fmaxf(v0.x, v0.y), fmaxf(v0.z, v0.w)),
                    fmaxf(fmaxf(v1.x, v1.y), fmaxf(v1.z, v1.w)));
    __shared__ float sm[8];
#pragma unroll
    for (int o = 16; o > 0; o >>= 1) m = fmaxf(m, __shfl_xor_sync(0xffffffffu, m, o));
    if ((tid & 31) == 0) sm[tid >> 5] = m;
    __syncthreads();
    if (tid < 32) {
        float t = (tid < 8) ? sm[tid] : -3.0e38f;
#pragma unroll
        for (int o = 4; o > 0; o >>= 1) t = fmaxf(t, __shfl_xor_sync(0xffffffffu, t, o));
        if (tid == 0) sm[0] = t;
    }
    __syncthreads();
    m = sm[0];
    __syncthreads();

    float e0 = __expf(v0.x - m), e1 = __expf(v0.y - m), e2 = __expf(v0.z - m), e3 = __expf(v0.w - m);
    float e4 = __expf(v1.x - m), e5 = __expf(v1.y - m), e6 = __expf(v1.z - m), e7 = __expf(v1.w - m);
    float s = ((e0 + e1) + (e2 + e3)) + ((e4 + e5) + (e6 + e7));
#pragma unroll
    for (int o = 16; o > 0; o >>= 1) s += __shfl_xor_sync(0xffffffffu, s, o);
    if ((tid & 31) == 0) sm[tid >> 5] = s;
    __syncthreads();
    if (tid < 32) {
        float t = (tid < 8) ? sm[tid] : 0.0f;
#pragma unroll
        for (int o = 4; o > 0; o >>= 1) t += __shfl_xor_sync(0xffffffffu, t, o);
        if (tid == 0) sm[0] = t;
    }
    __syncthreads();
    float inv = 1.0f / sm[0];

    *(float4*)(p + tid * 8)     = make_float4(e0 * inv, e1 * inv, e2 * inv, e3 * inv);
    *(float4*)(p + tid * 8 + 4) = make_float4(e4 * inv, e5 * inv, e6 * inv, e7 * inv);
}

// ---------------------------------------------------------------------------
// att GEMM: 128x64 tile, 2-stage B cp.async, A converted direct from global.
// 2 CTAs/SM cover the conversion latency. grid (16,1,32)
// ---------------------------------------------------------------------------
__global__ void __launch_bounds__(256, 2) gemm_att(const float* attn_arg)
{
    extern __shared__ char smem[];
    uint32_t sb = smem_u32(smem);
    int tid = threadIdx.x, wid = tid >> 5, lane = tid & 31;
    const float* attn = attn_arg ? attn_arg : g_attn_fb;
    int hb = blockIdx.z, h = hb >> 1, b = hb & 1;
    int m0 = blockIdx.x * 128;
    const float* A = attn + (size_t)hb * SN * SN + (size_t)m0 * SN;
    int wm = wid & 3, wn = wid >> 2;

    cp_tile(sb + 32768, g_vt_hi[hb], SN, tid, 64);
    cp_tile(sb + 40960, g_vt_lo[hb], SN, tid, 64);
    CP_COMMIT();

    float acc[2][4][4] = {};
#pragma unroll 1
    for (int s = 0; s < 32; s++) {
        uint32_t bs = sb + (s & 1) * NSTAGE;
        storeA_direct(bs, bs + 16384, A + s * 64, SN, tid);
        if (s < 31) {
            int kc = (s + 1) * 64;
            uint32_t nb = sb + ((s + 1) & 1) * NSTAGE;
            cp_tile(nb + 32768, g_vt_hi[hb] + kc, SN, tid, 64);
            cp_tile(nb + 40960, g_vt_lo[hb] + kc, SN, tid, 64);
            CP_COMMIT();
            CP_WAIT1();
        } else {
            CP_WAIT0();
        }
        __syncthreads();
        mma_chunk_64(acc, bs, wm, wn, lane);
        __syncthreads();
    }

    size_t rbase = (size_t)(b * SN + m0) + wm * 32;
    int cbase = h * EN + wn * 32;
#pragma unroll
    for (int mi = 0; mi < 2; mi++)
#pragma unroll
        for (int ni = 0; ni < 4; ni++) {
            size_t r0 = rbase + mi * 16 + (lane >> 2);
            int c = cbase + ni * 8 + (lane & 3) * 2;
            store_split2(g_cat_hi, g_cat_lo, r0 * DN + c,       acc[mi][ni][0], acc[mi][ni][1]);
            store_split2(g_cat_hi, g_cat_lo, (r0 + 8) * DN + c, acc[mi][ni][2], acc[mi][ni][3]);
        }
}

// ---------------------------------------------------------------------------
// Output GEMM: 128x64 tile, 2-stage, 2 CTAs/SM. grid (32, 16)
// ---------------------------------------------------------------------------
__global__ void __launch_bounds__(256, 2) gemm_out(float* __restrict__ out)
{
    extern __shared__ char smem[];
    uint32_t sb = smem_u32(smem);
    int tid = threadIdx.x, wid = tid >> 5, lane = tid & 31;
    int m0 = blockIdx.x * 128, n0 = blockIdx.y * 64;
    int wm = wid & 3, wn = wid >> 2;

    issue4_n64(sb, g_cat_hi + (size_t)m0 * DN, g_cat_lo + (size_t)m0 * DN,
               g_w_hi[3] + (size_t)n0 * DN, g_w_lo[3] + (size_t)n0 * DN, tid);
    CP_COMMIT();

    float acc[2][4][4] = {};
#pragma unroll 1
    for (int s = 0; s < 16; s++) {
        if (s < 15) {
            int kc = (s + 1) * 64;
            uint32_t nb = sb + ((s + 1) & 1) * NSTAGE;
            issue4_n64(nb, g_cat_hi + (size_t)m0 * DN + kc, g_cat_lo + (size_t)m0 * DN + kc,
                       g_w_hi[3] + (size_t)n0 * DN + kc, g_w_lo[3] + (size_t)n0 * DN + kc, tid);
            CP_COMMIT();
            CP_WAIT1();
        } else {
            CP_WAIT0();
        }
        __syncthreads();
        mma_chunk_64(acc, sb + (s & 1) * NSTAGE, wm, wn, lane);
        __syncthreads();
    }

    size_t rbase = (size_t)m0 + wm * 32;
    int cbase = n0 + wn * 32;
#pragma unroll
    for (int mi = 0; mi < 2; mi++)
#pragma unroll
        for (int ni = 0; ni < 4; ni++) {
            size_t r0 = rbase + mi * 16 + (lane >> 2);
            int c = cbase + ni * 8 + (lane & 3) * 2;
            *(float2*)(out + r0 * DN + c)       = make_float2(acc[mi][ni][0], acc[mi][ni][1]);
            *(float2*)(out + (r0 + 8) * DN + c) = make_float2(acc[mi][ni][2], acc[mi][ni][3]);
        }
}

// ---------------------------------------------------------------------------
extern "C" void kernel_launch(void* const* d_in, const int* in_sizes, int n_in,
                              void* d_out, int out_size)
{
    const float* acts[3] = {nullptr, nullptr, nullptr};
    const float* wts[4]  = {nullptr, nullptr, nullptr, nullptr};
    int na = 0, nw = 0;
    for (int i = 0; i < n_in; i++) {
        if (in_sizes[i] == BSN * DN && na < 3) acts[na++] = (const float*)d_in[i];
        else if (nw < 4)                       wts[nw++]  = (const float*)d_in[i];
    }
    if (na != 3 || nw != 4) {
        acts[0] = (const float*)d_in[0]; acts[1] = (const float*)d_in[1]; acts[2] = (const float*)d_in[2];
        wts[0]  = (const float*)d_in[3]; wts[1]  = (const float*)d_in[4];
        wts[2]  = (const float*)d_in[5]; wts[3]  = (const float*)d_in[6];
    }
    const float* q  = acts[0];
    const float* k  = acts[1];
    const float* v  = acts[2];
    const float* Wq = wts[0];
    const float* Wk = wts[1];
    const float* Wv = wts[2];
    const float* Wo = wts[3];
    float* out = (float*)d_out;

    const long long OUT_E  = (long long)BSN * DN;
    const long long ATTN_E = (long long)HBN * SN * SN;
    float* attn_ptr = ((long long)out_size >= OUT_E + ATTN_E) ? (out + OUT_E) : nullptr;

    cudaFuncSetAttribute(gemm_proj,   cudaFuncAttributeMaxDynamicSharedMemorySize, SMEM_N64X2);
    cudaFuncSetAttribute(gemm_scores, cudaFuncAttributeMaxDynamicSharedMemorySize, SMEM_SCORES);
    cudaFuncSetAttribute(gemm_att,    cudaFuncAttributeMaxDynamicSharedMemorySize, SMEM_N64X2);
    cudaFuncSetAttribute(gemm_out,    cudaFuncAttributeMaxDynamicSharedMemorySize, SMEM_N64X2);

    xsplit_kernel<<<dim3(2048, 3), 256>>>(q, k, v);
    wsplit_qkv<<<dim3(32, 2, 48), dim3(32, 8)>>>(Wq, Wk, Wv);
    wsplit_o<<<dim3(32, 32), dim3(32, 8)>>>(Wo);
    gemm_proj<<<dim3(32, 16, 3), 256, SMEM_N64X2>>>(0);
    vtrans_kernel<<<dim3(64, 2, 32), dim3(32, 8)>>>();
    gemm_scores<<<dim3(16, 16, 32), 256, SMEM_SCORES>>>(attn_ptr);
    softmax_kernel<<<dim3(HBN * SN), 256>>>(attn_ptr);
    gemm_att<<<dim3(16, 1, 32), 256, SMEM_N64X2>>>(attn_ptr);
    gemm_out<<<dim3(32, 16), 256, SMEM_N64X2>>>(out);
}